// round 9
// baseline (speedup 1.0000x reference)
#include <cuda_runtime.h>
#include <cuda_bf16.h>
#include <cstdint>

#define V_TOTAL 267735
#define NROWS   512
#define YSTRIDE 1360   // 1024 + 256 + 64 + 16

// ---------------- device scratch (no allocations allowed) ----------------
__device__ float          g_Yf[NROWS * YSTRIDE];     // fp32 projections
__device__ __nv_bfloat16  g_Yh[NROWS * YSTRIDE];     // bf16 projections
__device__ float          g_rowsum[4 * NROWS];       // sum(exp(logit)) per region/row
__device__ float          g_SUB[4 * NROWS];          // per-region per-row subtract term

// ---------------- K0: zero the row sums ----------------
__global__ void k_zero() {
    int i = blockIdx.x * blockDim.x + threadIdx.x;
    if (i < 4 * NROWS) g_rowsum[i] = 0.f;
}

// ---------------- K1: projections  Y = H(512x1024) @ P^T (E x 1024), fp32 ----
__global__ void k_proj(const float* __restrict__ H, const float* __restrict__ P,
                       int E, int yofs) {
    __shared__ float As[16][66];
    __shared__ float Bs[16][66];
    const int tid = threadIdx.x;
    const int tx = tid & 15, ty = tid >> 4;
    const int m0 = blockIdx.y * 64, n0 = blockIdx.x * 64;

    float acc[4][4];
#pragma unroll
    for (int i = 0; i < 4; i++)
#pragma unroll
        for (int j = 0; j < 4; j++) acc[i][j] = 0.f;

    for (int k0 = 0; k0 < 1024; k0 += 16) {
#pragma unroll
        for (int i = 0; i < 4; i++) {
            int e = tid + i * 256;
            int r = e >> 4, c = e & 15;
            As[c][r] = H[(size_t)(m0 + r) * 1024 + k0 + c];
            int nn = n0 + r;
            Bs[c][r] = (nn < E) ? P[(size_t)nn * 1024 + k0 + c] : 0.f;
        }
        __syncthreads();
#pragma unroll
        for (int k = 0; k < 16; k++) {
            float am[4], bn[4];
#pragma unroll
            for (int i = 0; i < 4; i++) am[i] = As[k][ty * 4 + i];
#pragma unroll
            for (int j = 0; j < 4; j++) bn[j] = Bs[k][tx * 4 + j];
#pragma unroll
            for (int i = 0; i < 4; i++)
#pragma unroll
                for (int j = 0; j < 4; j++) acc[i][j] += am[i] * bn[j];
        }
        __syncthreads();
    }
#pragma unroll
    for (int i = 0; i < 4; i++) {
        int m = m0 + ty * 4 + i;
#pragma unroll
        for (int j = 0; j < 4; j++) {
            int n = n0 + tx * 4 + j;
            if (n < E) {
                size_t idx = (size_t)m * YSTRIDE + yofs + n;
                g_Yf[idx] = acc[i][j];
                g_Yh[idx] = __float2bfloat16(acc[i][j]);
            }
        }
    }
}

// ---------------- K2: logits GEMM (bf16 mma) + fused exp-sum ----------------
// block tile: 64 rows x 128 cols, 8 warps (2 along M x 4 along N), warp 32x32.
// A (y, bf16) staged once in smem (full K). B fragments loaded directly from
// global fp32 W and converted in registers.
__global__ void k_logits(const float* __restrict__ W, const float* __restrict__ b,
                         float* __restrict__ out,
                         int N, int K, int yofs, int colBase, int region) {
    extern __shared__ char smem_raw[];
    __nv_bfloat16* As = (__nv_bfloat16*)smem_raw;
    const int LDA = K + 8;

    const int tid  = threadIdx.x;
    const int lane = tid & 31, wid = tid >> 5;
    const int mBlk = blockIdx.x * 64;
    const int nBlk = blockIdx.y * 128;

    // ---- stage A tile (64 x K bf16), 16B chunks, conflict-safe layout ----
    {
        const int cpr = K >> 3;  // uint4 chunks per row
        for (int r = wid * 8; r < wid * 8 + 8; r++) {
            const uint4* src = (const uint4*)(g_Yh + (size_t)(mBlk + r) * YSTRIDE + yofs);
            uint4* dst = (uint4*)(As + r * LDA);
            for (int c = lane; c < cpr; c += 32) dst[c] = src[c];
        }
    }
    __syncthreads();

    const int wm  = wid & 1;      // 0..1 (M)
    const int wn  = wid >> 1;     // 0..3 (N)
    const int qr  = lane >> 2;    // 0..7
    const int qc2 = (lane & 3) * 2;

    float acc[2][4][4];
#pragma unroll
    for (int mt = 0; mt < 2; mt++)
#pragma unroll
        for (int nt = 0; nt < 4; nt++)
#pragma unroll
            for (int c = 0; c < 4; c++) acc[mt][nt][c] = 0.f;

    int  nIdx[4];
    bool nValid[4];
#pragma unroll
    for (int nt = 0; nt < 4; nt++) {
        nIdx[nt]   = nBlk + wn * 32 + nt * 8 + qr;
        nValid[nt] = nIdx[nt] < N;
    }

    const int NK = K >> 4;
    float2 fB[4][2];
#pragma unroll
    for (int nt = 0; nt < 4; nt++) {
        if (nValid[nt]) {
            const float* wp = W + (size_t)nIdx[nt] * K + qc2;
            fB[nt][0] = *(const float2*)(wp);
            fB[nt][1] = *(const float2*)(wp + 8);
        } else {
            fB[nt][0] = make_float2(0.f, 0.f);
            fB[nt][1] = make_float2(0.f, 0.f);
        }
    }

    for (int ks = 0; ks < NK; ks++) {
        const int k0 = ks * 16;
        float2 nxt[4][2];
        if (ks + 1 < NK) {
#pragma unroll
            for (int nt = 0; nt < 4; nt++) {
                if (nValid[nt]) {
                    const float* wp = W + (size_t)nIdx[nt] * K + k0 + 16 + qc2;
                    nxt[nt][0] = *(const float2*)(wp);
                    nxt[nt][1] = *(const float2*)(wp + 8);
                } else {
                    nxt[nt][0] = make_float2(0.f, 0.f);
                    nxt[nt][1] = make_float2(0.f, 0.f);
                }
            }
        }

        uint32_t a[2][4];
#pragma unroll
        for (int mt = 0; mt < 2; mt++) {
            const __nv_bfloat16* ap = As + (wm * 32 + mt * 16 + qr) * LDA + k0 + qc2;
            a[mt][0] = *(const uint32_t*)(ap);
            a[mt][1] = *(const uint32_t*)(ap + 8 * LDA);
            a[mt][2] = *(const uint32_t*)(ap + 8);
            a[mt][3] = *(const uint32_t*)(ap + 8 * LDA + 8);
        }

        uint32_t bfr[4][2];
#pragma unroll
        for (int nt = 0; nt < 4; nt++)
#pragma unroll
            for (int h = 0; h < 2; h++) {
                __nv_bfloat162 hv = __floats2bfloat162_rn(fB[nt][h].x, fB[nt][h].y);
                bfr[nt][h] = *reinterpret_cast<uint32_t*>(&hv);
            }

#pragma unroll
        for (int mt = 0; mt < 2; mt++)
#pragma unroll
            for (int nt = 0; nt < 4; nt++) {
                asm volatile(
                    "mma.sync.aligned.m16n8k16.row.col.f32.bf16.bf16.f32 "
                    "{%0,%1,%2,%3}, {%4,%5,%6,%7}, {%8,%9}, {%0,%1,%2,%3};\n"
                    : "+f"(acc[mt][nt][0]), "+f"(acc[mt][nt][1]),
                      "+f"(acc[mt][nt][2]), "+f"(acc[mt][nt][3])
                    : "r"(a[mt][0]), "r"(a[mt][1]), "r"(a[mt][2]), "r"(a[mt][3]),
                      "r"(bfr[nt][0]), "r"(bfr[nt][1]));
            }

        if (ks + 1 < NK) {
#pragma unroll
            for (int nt = 0; nt < 4; nt++) {
                fB[nt][0] = nxt[nt][0];
                fB[nt][1] = nxt[nt][1];
            }
        }
    }

    // ---- epilogue: store logits + per-row exp-sums ----
    __syncthreads();
    float* srow = (float*)smem_raw;  // reuse smem: 64 per-row partial sums
    if (tid < 64) srow[tid] = 0.f;
    __syncthreads();

#pragma unroll
    for (int mt = 0; mt < 2; mt++) {
#pragma unroll
        for (int hh = 0; hh < 2; hh++) {
            int rloc = wm * 32 + mt * 16 + qr + hh * 8;
            size_t rgl = (size_t)(mBlk + rloc);
            float part = 0.f;
#pragma unroll
            for (int nt = 0; nt < 4; nt++) {
                int n0 = nBlk + wn * 32 + nt * 8 + qc2;
#pragma unroll
                for (int p = 0; p < 2; p++) {
                    int n = n0 + p;
                    if (n < N) {
                        float v = acc[mt][nt][hh * 2 + p] + b[n];
                        out[rgl * V_TOTAL + colBase + n] = v;
                        part += __expf(v);
                    }
                }
            }
            // lanes sharing a row differ only in (lane & 3)
            part += __shfl_xor_sync(0xffffffffu, part, 1);
            part += __shfl_xor_sync(0xffffffffu, part, 2);
            if ((lane & 3) == 0) atomicAdd(&srow[rloc], part);
        }
    }
    __syncthreads();
    if (tid < 64)
        atomicAdd(&g_rowsum[region * NROWS + mBlk + tid], srow[tid]);
}

// ---------------- K3: cluster logits + per-region subtract terms ----------------
__global__ void k_head_fix(const float* __restrict__ cw, const float* __restrict__ cb) {
    const int row = blockIdx.x;
    const int tid = threadIdx.x;  // 128
    __shared__ float red[3][128];
    float p0 = 0.f, p1 = 0.f, p2 = 0.f;
    const float* y = g_Yf + (size_t)row * YSTRIDE;  // y0, K=1024
    for (int e = tid; e < 1024; e += 128) {
        float yv = y[e];
        p0 += yv * cw[e];
        p1 += yv * cw[1024 + e];
        p2 += yv * cw[2048 + e];
    }
    red[0][tid] = p0; red[1][tid] = p1; red[2][tid] = p2;
    __syncthreads();
    for (int s = 64; s > 0; s >>= 1) {
        if (tid < s) {
            red[0][tid] += red[0][tid + s];
            red[1][tid] += red[1][tid + s];
            red[2][tid] += red[2][tid + s];
        }
        __syncthreads();
    }
    if (tid == 0) {
        float c0 = red[0][0] + cb[0];
        float c1 = red[1][0] + cb[1];
        float c2 = red[2][0] + cb[2];
        float s = g_rowsum[row] + __expf(c0) + __expf(c1) + __expf(c2);
        float lse0 = logf(s);
        g_SUB[row] = lse0;                       // head: out = logit - lse0
        float cl[3] = {c0 - lse0, c1 - lse0, c2 - lse0};
        for (int i = 1; i < 4; i++)              // tail: out = logit - lse_i + cl[i-1]
            g_SUB[i * NROWS + row] = logf(g_rowsum[i * NROWS + row]) - cl[i - 1];
    }
}

// ---------------- K4: vectorized subtract over the whole output ----------------
__global__ void k_sub(float* __restrict__ out, unsigned int total4) {
    unsigned int i4 = blockIdx.x * blockDim.x + threadIdx.x;
    if (i4 >= total4) return;
    unsigned int e = i4 * 4u;
    unsigned int row = e / (unsigned)V_TOTAL;
    unsigned int col = e - row * (unsigned)V_TOTAL;
    float4 v = *((const float4*)out + i4);
    float vv[4] = {v.x, v.y, v.z, v.w};
#pragma unroll
    for (int j = 0; j < 4; j++) {
        if (col >= (unsigned)V_TOTAL) { col -= (unsigned)V_TOTAL; row++; }
        int reg = (col < 20000u) ? 0 : (col < 40000u) ? 1 : (col < 200000u) ? 2 : 3;
        vv[j] -= g_SUB[reg * NROWS + row];
        col++;
    }
    v.x = vv[0]; v.y = vv[1]; v.z = vv[2]; v.w = vv[3];
    *((float4*)out + i4) = v;
}

// ---------------- K5: loss = mean(-lp[target]) ----------------
__global__ void k_loss(const float* __restrict__ out, const int* __restrict__ tgt,
                       float* __restrict__ loss_out) {
    __shared__ float red[512];
    int r = threadIdx.x;
    int t = tgt[r];
    red[r] = -out[(size_t)r * V_TOTAL + t];
    __syncthreads();
    for (int s = 256; s > 0; s >>= 1) {
        if (r < s) red[r] += red[r + s];
        __syncthreads();
    }
    if (r == 0) *loss_out = red[0] / 512.f;
}

// ---------------- launch ----------------
extern "C" void kernel_launch(void* const* d_in, const int* in_sizes, int n_in,
                              void* d_out, int out_size) {
    const float* hidden = (const float*)d_in[0];
    const int*   target = (const int*)d_in[1];
    const float* cw     = (const float*)d_in[2];
    const float* cb     = (const float*)d_in[3];
    const float* W[4]  = {(const float*)d_in[4],  (const float*)d_in[7],
                          (const float*)d_in[10], (const float*)d_in[13]};
    const float* bb[4] = {(const float*)d_in[5],  (const float*)d_in[8],
                          (const float*)d_in[11], (const float*)d_in[14]};
    const float* P[4]  = {(const float*)d_in[6],  (const float*)d_in[9],
                          (const float*)d_in[12], (const float*)d_in[15]};
    float* out = (float*)d_out;

    static const int Ns[4]      = {20000, 20000, 160000, 67735};
    static const int Ks[4]      = {1024, 256, 64, 16};
    static const int yofs[4]    = {0, 1024, 1280, 1344};
    static const int colBase[4] = {0, 20000, 40000, 200000};

    cudaFuncSetAttribute(k_logits, cudaFuncAttributeMaxDynamicSharedMemorySize,
                         64 * (1024 + 8) * 2);

    k_zero<<<8, 256>>>();

    for (int i = 0; i < 4; i++)
        k_proj<<<dim3((Ks[i] + 63) / 64, 8), 256>>>(hidden, P[i], Ks[i], yofs[i]);

    for (int i = 0; i < 4; i++) {
        dim3 grid(8, (Ns[i] + 127) / 128);   // mtile fast-varying -> W reuse in L2
        int smem = 64 * (Ks[i] + 8) * 2;
        k_logits<<<grid, 256, smem>>>(W[i], bb[i], out, Ns[i], Ks[i],
                                      yofs[i], colBase[i], i);
    }

    k_head_fix<<<512, 128>>>(cw, cb);

    unsigned int total4 = (unsigned int)NROWS * (unsigned int)V_TOTAL / 4u;
    k_sub<<<(total4 + 255u) / 256u, 256>>>(out, total4);

    k_loss<<<1, 512>>>(out, target, out + (size_t)out_size - 1);
}

// round 10
// speedup vs baseline: 1.0748x; 1.0748x over previous
#include <cuda_runtime.h>
#include <cuda_bf16.h>
#include <cstdint>

#define V_TOTAL 267735
#define NROWS   512
#define YSTRIDE 1360   // 1024 + 256 + 64 + 16

// ---------------- device scratch (no allocations allowed) ----------------
__device__ float          g_Yf[NROWS * YSTRIDE];     // fp32 projections (head cluster logits)
__device__ __nv_bfloat16  g_Yh[NROWS * YSTRIDE];     // bf16 projections (GEMM A operand)
__device__ float          g_rowsum[4 * NROWS];       // sum(exp(logit)) per region/row
__device__ float          g_SUB[4 * NROWS];          // per-region per-row subtract term

// ---------------- K0: zero the row sums ----------------
__global__ void k_zero() {
    int i = blockIdx.x * blockDim.x + threadIdx.x;
    if (i < 4 * NROWS) g_rowsum[i] = 0.f;
}

// ---------------- K1: ALL projections fused: Y = H(512x1024) @ Pcat^T ----
// grid = (22 ntiles, 8 mtiles); ntile -> region lookup.
__global__ void k_proj_all(const float* __restrict__ H,
                           const float* __restrict__ P0, const float* __restrict__ P1,
                           const float* __restrict__ P2, const float* __restrict__ P3) {
    __shared__ float As[16][66];
    __shared__ float Bs[16][66];

    const int nt = blockIdx.x;
    const float* P; int E, yofs, n0;
    if (nt < 16)       { P = P0; E = 1024; yofs = 0;    n0 = nt * 64; }
    else if (nt < 20)  { P = P1; E = 256;  yofs = 1024; n0 = (nt - 16) * 64; }
    else if (nt == 20) { P = P2; E = 64;   yofs = 1280; n0 = 0; }
    else               { P = P3; E = 16;   yofs = 1344; n0 = 0; }

    const int tid = threadIdx.x;
    const int tx = tid & 15, ty = tid >> 4;
    const int m0 = blockIdx.y * 64;

    float acc[4][4];
#pragma unroll
    for (int i = 0; i < 4; i++)
#pragma unroll
        for (int j = 0; j < 4; j++) acc[i][j] = 0.f;

    for (int k0 = 0; k0 < 1024; k0 += 16) {
#pragma unroll
        for (int i = 0; i < 4; i++) {
            int e = tid + i * 256;
            int r = e >> 4, c = e & 15;
            As[c][r] = H[(size_t)(m0 + r) * 1024 + k0 + c];
            int nn = n0 + r;
            Bs[c][r] = (nn < E) ? P[(size_t)nn * 1024 + k0 + c] : 0.f;
        }
        __syncthreads();
#pragma unroll
        for (int k = 0; k < 16; k++) {
            float am[4], bn[4];
#pragma unroll
            for (int i = 0; i < 4; i++) am[i] = As[k][ty * 4 + i];
#pragma unroll
            for (int j = 0; j < 4; j++) bn[j] = Bs[k][tx * 4 + j];
#pragma unroll
            for (int i = 0; i < 4; i++)
#pragma unroll
                for (int j = 0; j < 4; j++) acc[i][j] += am[i] * bn[j];
        }
        __syncthreads();
    }
#pragma unroll
    for (int i = 0; i < 4; i++) {
        int m = m0 + ty * 4 + i;
#pragma unroll
        for (int j = 0; j < 4; j++) {
            int n = n0 + tx * 4 + j;
            if (n < E) {
                size_t idx = (size_t)m * YSTRIDE + yofs + n;
                g_Yf[idx] = acc[i][j];
                g_Yh[idx] = __float2bfloat16(acc[i][j]);
            }
        }
    }
}

// ---------------- K2: logits GEMM (bf16 mma), three modes ----------------
// mode 0: store RAW logits to out + accumulate rowsums   (regions 0,1 pass 1)
// mode 1: rowsums only, no store                          (regions 2,3 pass 1)
// mode 2: store FINAL (logit - SUB), no rowsums           (regions 2,3 pass 2)
// block: 64 rows x 128 cols, 8 warps (2M x 4N), warp tile 32x32.
__global__ void k_logits(const float* __restrict__ W, const float* __restrict__ b,
                         float* __restrict__ out,
                         int N, int K, int yofs, int colBase, int region, int mode) {
    extern __shared__ char smem_raw[];
    __nv_bfloat16* As = (__nv_bfloat16*)smem_raw;
    // row stride in 4B words must be == 12 (mod 32) for conflict-free mma A loads
    const int LDA = ((K >> 6) << 6) + 24;

    const int tid  = threadIdx.x;
    const int lane = tid & 31, wid = tid >> 5;
    const int mBlk = blockIdx.x * 64;
    const int nBlk = blockIdx.y * 128;

    // ---- stage A tile (64 x K bf16) ----
    {
        const int cpr = K >> 3;  // uint4 chunks per row
        for (int r = wid * 8; r < wid * 8 + 8; r++) {
            const uint4* src = (const uint4*)(g_Yh + (size_t)(mBlk + r) * YSTRIDE + yofs);
            uint4* dst = (uint4*)(As + r * LDA);
            for (int c = lane; c < cpr; c += 32) dst[c] = src[c];
        }
    }
    __syncthreads();

    const int wm  = wid & 1;      // M warp
    const int wn  = wid >> 1;     // N warp
    const int qr  = lane >> 2;    // 0..7
    const int qc2 = (lane & 3) * 2;

    float acc[2][4][4];
#pragma unroll
    for (int mt = 0; mt < 2; mt++)
#pragma unroll
        for (int nt = 0; nt < 4; nt++)
#pragma unroll
            for (int c = 0; c < 4; c++) acc[mt][nt][c] = 0.f;

    int  nIdx[4];
    bool nValid[4];
#pragma unroll
    for (int nt = 0; nt < 4; nt++) {
        nIdx[nt]   = nBlk + wn * 32 + nt * 8 + qr;
        nValid[nt] = nIdx[nt] < N;
    }

    const int NK = K >> 4;
    float2 fB[4][2];
#pragma unroll
    for (int nt = 0; nt < 4; nt++) {
        if (nValid[nt]) {
            const float* wp = W + (size_t)nIdx[nt] * K + qc2;
            fB[nt][0] = *(const float2*)(wp);
            fB[nt][1] = *(const float2*)(wp + 8);
        } else {
            fB[nt][0] = make_float2(0.f, 0.f);
            fB[nt][1] = make_float2(0.f, 0.f);
        }
    }

    for (int ks = 0; ks < NK; ks++) {
        const int k0 = ks * 16;
        float2 nxt[4][2];
        if (ks + 1 < NK) {
#pragma unroll
            for (int nt = 0; nt < 4; nt++) {
                if (nValid[nt]) {
                    const float* wp = W + (size_t)nIdx[nt] * K + k0 + 16 + qc2;
                    nxt[nt][0] = *(const float2*)(wp);
                    nxt[nt][1] = *(const float2*)(wp + 8);
                } else {
                    nxt[nt][0] = make_float2(0.f, 0.f);
                    nxt[nt][1] = make_float2(0.f, 0.f);
                }
            }
        }

        uint32_t a[2][4];
#pragma unroll
        for (int mt = 0; mt < 2; mt++) {
            const __nv_bfloat16* ap = As + (wm * 32 + mt * 16 + qr) * LDA + k0 + qc2;
            a[mt][0] = *(const uint32_t*)(ap);
            a[mt][1] = *(const uint32_t*)(ap + 8 * LDA);
            a[mt][2] = *(const uint32_t*)(ap + 8);
            a[mt][3] = *(const uint32_t*)(ap + 8 * LDA + 8);
        }

        uint32_t bfr[4][2];
#pragma unroll
        for (int nt = 0; nt < 4; nt++)
#pragma unroll
            for (int h = 0; h < 2; h++) {
                __nv_bfloat162 hv = __floats2bfloat162_rn(fB[nt][h].x, fB[nt][h].y);
                bfr[nt][h] = *reinterpret_cast<uint32_t*>(&hv);
            }

#pragma unroll
        for (int mt = 0; mt < 2; mt++)
#pragma unroll
            for (int nt = 0; nt < 4; nt++) {
                asm volatile(
                    "mma.sync.aligned.m16n8k16.row.col.f32.bf16.bf16.f32 "
                    "{%0,%1,%2,%3}, {%4,%5,%6,%7}, {%8,%9}, {%0,%1,%2,%3};\n"
                    : "+f"(acc[mt][nt][0]), "+f"(acc[mt][nt][1]),
                      "+f"(acc[mt][nt][2]), "+f"(acc[mt][nt][3])
                    : "r"(a[mt][0]), "r"(a[mt][1]), "r"(a[mt][2]), "r"(a[mt][3]),
                      "r"(bfr[nt][0]), "r"(bfr[nt][1]));
            }

        if (ks + 1 < NK) {
#pragma unroll
            for (int nt = 0; nt < 4; nt++) {
                fB[nt][0] = nxt[nt][0];
                fB[nt][1] = nxt[nt][1];
            }
        }
    }

    // ---- epilogue ----
    __syncthreads();

    if (mode == 2) {
        // final store: out = logit + bias - SUB[region][row]
#pragma unroll
        for (int mt = 0; mt < 2; mt++) {
#pragma unroll
            for (int hh = 0; hh < 2; hh++) {
                int rloc = wm * 32 + mt * 16 + qr + hh * 8;
                size_t rgl = (size_t)(mBlk + rloc);
                float sub = g_SUB[region * NROWS + rgl];
#pragma unroll
                for (int nt = 0; nt < 4; nt++) {
                    int n0 = nBlk + wn * 32 + nt * 8 + qc2;
#pragma unroll
                    for (int p = 0; p < 2; p++) {
                        int n = n0 + p;
                        if (n < N)
                            out[rgl * V_TOTAL + colBase + n] =
                                acc[mt][nt][hh * 2 + p] + b[n] - sub;
                    }
                }
            }
        }
        return;
    }

    // modes 0/1: per-row exp-sums (+ raw store if mode 0)
    float* srow = (float*)smem_raw;  // reuse smem
    if (tid < 64) srow[tid] = 0.f;
    __syncthreads();

#pragma unroll
    for (int mt = 0; mt < 2; mt++) {
#pragma unroll
        for (int hh = 0; hh < 2; hh++) {
            int rloc = wm * 32 + mt * 16 + qr + hh * 8;
            size_t rgl = (size_t)(mBlk + rloc);
            float part = 0.f;
#pragma unroll
            for (int nt = 0; nt < 4; nt++) {
                int n0 = nBlk + wn * 32 + nt * 8 + qc2;
#pragma unroll
                for (int p = 0; p < 2; p++) {
                    int n = n0 + p;
                    if (n < N) {
                        float v = acc[mt][nt][hh * 2 + p] + b[n];
                        if (mode == 0)
                            out[rgl * V_TOTAL + colBase + n] = v;
                        part += __expf(v);
                    }
                }
            }
            part += __shfl_xor_sync(0xffffffffu, part, 1);
            part += __shfl_xor_sync(0xffffffffu, part, 2);
            if ((lane & 3) == 0) atomicAdd(&srow[rloc], part);
        }
    }
    __syncthreads();
    if (tid < 64)
        atomicAdd(&g_rowsum[region * NROWS + mBlk + tid], srow[tid]);
}

// ---------------- K3: cluster logits + per-region subtract terms ----------------
__global__ void k_head_fix(const float* __restrict__ cw, const float* __restrict__ cb) {
    const int row = blockIdx.x;
    const int tid = threadIdx.x;  // 128
    __shared__ float red[3][128];
    float p0 = 0.f, p1 = 0.f, p2 = 0.f;
    const float* y = g_Yf + (size_t)row * YSTRIDE;  // y0, K=1024
    for (int e = tid; e < 1024; e += 128) {
        float yv = y[e];
        p0 += yv * cw[e];
        p1 += yv * cw[1024 + e];
        p2 += yv * cw[2048 + e];
    }
    red[0][tid] = p0; red[1][tid] = p1; red[2][tid] = p2;
    __syncthreads();
    for (int s = 64; s > 0; s >>= 1) {
        if (tid < s) {
            red[0][tid] += red[0][tid + s];
            red[1][tid] += red[1][tid + s];
            red[2][tid] += red[2][tid + s];
        }
        __syncthreads();
    }
    if (tid == 0) {
        float c0 = red[0][0] + cb[0];
        float c1 = red[1][0] + cb[1];
        float c2 = red[2][0] + cb[2];
        float s = g_rowsum[row] + __expf(c0) + __expf(c1) + __expf(c2);
        float lse0 = logf(s);
        g_SUB[row] = lse0;                       // head: out = logit - lse0
        float cl[3] = {c0 - lse0, c1 - lse0, c2 - lse0};
        for (int i = 1; i < 4; i++)              // tail: out = logit - lse_i + cl[i-1]
            g_SUB[i * NROWS + row] = logf(g_rowsum[i * NROWS + row]) - cl[i - 1];
    }
}

// ---------------- K4: subtract over regions 0/1 only (cols < 40000) ----------------
__global__ void k_sub01(float* __restrict__ out) {
    int i = blockIdx.x * blockDim.x + threadIdx.x;
    if (i >= NROWS * 40000) return;
    int row = i / 40000;
    int col = i - row * 40000;
    int reg = (col < 20000) ? 0 : 1;
    out[(size_t)row * V_TOTAL + col] -= g_SUB[reg * NROWS + row];
}

// ---------------- K5: loss = mean(-lp[target]) ----------------
__global__ void k_loss(const float* __restrict__ out, const int* __restrict__ tgt,
                       float* __restrict__ loss_out) {
    __shared__ float red[512];
    int r = threadIdx.x;
    int t = tgt[r];
    red[r] = -out[(size_t)r * V_TOTAL + t];
    __syncthreads();
    for (int s = 256; s > 0; s >>= 1) {
        if (r < s) red[r] += red[r + s];
        __syncthreads();
    }
    if (r == 0) *loss_out = red[0] / 512.f;
}

// ---------------- launch ----------------
extern "C" void kernel_launch(void* const* d_in, const int* in_sizes, int n_in,
                              void* d_out, int out_size) {
    const float* hidden = (const float*)d_in[0];
    const int*   target = (const int*)d_in[1];
    const float* cw     = (const float*)d_in[2];
    const float* cb     = (const float*)d_in[3];
    const float* W[4]  = {(const float*)d_in[4],  (const float*)d_in[7],
                          (const float*)d_in[10], (const float*)d_in[13]};
    const float* bb[4] = {(const float*)d_in[5],  (const float*)d_in[8],
                          (const float*)d_in[11], (const float*)d_in[14]};
    const float* P[4]  = {(const float*)d_in[6],  (const float*)d_in[9],
                          (const float*)d_in[12], (const float*)d_in[15]};
    float* out = (float*)d_out;

    static const int Ns[4]      = {20000, 20000, 160000, 67735};
    static const int Ks[4]      = {1024, 256, 64, 16};
    static const int yofs[4]    = {0, 1024, 1280, 1344};
    static const int colBase[4] = {0, 20000, 40000, 200000};

    auto smem_for = [](int K) { return 64 * (((K >> 6) << 6) + 24) * 2; };
    cudaFuncSetAttribute(k_logits, cudaFuncAttributeMaxDynamicSharedMemorySize,
                         smem_for(1024));

    k_zero<<<8, 256>>>();

    // all projections in one launch (22 ntiles x 8 mtiles = 176 blocks)
    k_proj_all<<<dim3(22, 8), 256>>>(hidden, P[0], P[1], P[2], P[3]);

    // pass 1: r0/r1 store raw + rowsum (mode 0); r2/r3 rowsum only (mode 1)
    for (int i = 0; i < 4; i++) {
        dim3 grid(8, (Ns[i] + 127) / 128);   // mtile fast-varying -> W reuse in L2
        int mode = (i < 2) ? 0 : 1;
        k_logits<<<grid, 256, smem_for(Ks[i])>>>(W[i], bb[i], out, Ns[i], Ks[i],
                                                 yofs[i], colBase[i], i, mode);
    }

    k_head_fix<<<512, 128>>>(cw, cb);

    // pass 2: subtract for r0/r1; recompute+final store for r2/r3 (mode 2)
    k_sub01<<<(NROWS * 40000 + 255) / 256, 256>>>(out);
    for (int i = 2; i < 4; i++) {
        dim3 grid(8, (Ns[i] + 127) / 128);
        k_logits<<<grid, 256, smem_for(Ks[i])>>>(W[i], bb[i], out, Ns[i], Ks[i],
                                                 yofs[i], colBase[i], i, 2);
    }

    k_loss<<<1, 512>>>(out, target, out + (size_t)out_size - 1);
}

// round 11
// speedup vs baseline: 1.0823x; 1.0070x over previous
#include <cuda_runtime.h>
#include <cuda_bf16.h>
#include <cstdint>

#define V_TOTAL 267735
#define NROWS   512
#define YSTRIDE 1360   // 1024 + 256 + 64 + 16

// ---------------- device scratch (no allocations allowed) ----------------
__device__ float          g_Yf[NROWS * YSTRIDE];     // fp32 projections (head cluster logits)
__device__ __nv_bfloat16  g_Yh[NROWS * YSTRIDE];     // bf16 projections (GEMM A operand)
__device__ float          g_rowsum[4 * NROWS];       // sum(exp(logit)) per region/row
__device__ float          g_SUB[4 * NROWS];          // per-region per-row subtract term

// ---------------- K0: zero the row sums ----------------
__global__ void k_zero() {
    int i = blockIdx.x * blockDim.x + threadIdx.x;
    if (i < 4 * NROWS) g_rowsum[i] = 0.f;
}

// ---------------- K1: ALL projections fused: Y = H(512x1024) @ Pcat^T ----
// grid = (22 ntiles, 8 mtiles); ntile -> region lookup.
__global__ void k_proj_all(const float* __restrict__ H,
                           const float* __restrict__ P0, const float* __restrict__ P1,
                           const float* __restrict__ P2, const float* __restrict__ P3) {
    __shared__ float As[16][66];
    __shared__ float Bs[16][66];

    const int nt = blockIdx.x;
    const float* P; int E, yofs, n0;
    if (nt < 16)       { P = P0; E = 1024; yofs = 0;    n0 = nt * 64; }
    else if (nt < 20)  { P = P1; E = 256;  yofs = 1024; n0 = (nt - 16) * 64; }
    else if (nt == 20) { P = P2; E = 64;   yofs = 1280; n0 = 0; }
    else               { P = P3; E = 16;   yofs = 1344; n0 = 0; }

    const int tid = threadIdx.x;
    const int tx = tid & 15, ty = tid >> 4;
    const int m0 = blockIdx.y * 64;

    float acc[4][4];
#pragma unroll
    for (int i = 0; i < 4; i++)
#pragma unroll
        for (int j = 0; j < 4; j++) acc[i][j] = 0.f;

    for (int k0 = 0; k0 < 1024; k0 += 16) {
#pragma unroll
        for (int i = 0; i < 4; i++) {
            int e = tid + i * 256;
            int r = e >> 4, c = e & 15;
            As[c][r] = H[(size_t)(m0 + r) * 1024 + k0 + c];
            int nn = n0 + r;
            Bs[c][r] = (nn < E) ? P[(size_t)nn * 1024 + k0 + c] : 0.f;
        }
        __syncthreads();
#pragma unroll
        for (int k = 0; k < 16; k++) {
            float am[4], bn[4];
#pragma unroll
            for (int i = 0; i < 4; i++) am[i] = As[k][ty * 4 + i];
#pragma unroll
            for (int j = 0; j < 4; j++) bn[j] = Bs[k][tx * 4 + j];
#pragma unroll
            for (int i = 0; i < 4; i++)
#pragma unroll
                for (int j = 0; j < 4; j++) acc[i][j] += am[i] * bn[j];
        }
        __syncthreads();
    }
#pragma unroll
    for (int i = 0; i < 4; i++) {
        int m = m0 + ty * 4 + i;
#pragma unroll
        for (int j = 0; j < 4; j++) {
            int n = n0 + tx * 4 + j;
            if (n < E) {
                size_t idx = (size_t)m * YSTRIDE + yofs + n;
                g_Yf[idx] = acc[i][j];
                g_Yh[idx] = __float2bfloat16(acc[i][j]);
            }
        }
    }
}

// ---------------- K2: logits GEMM (bf16 mma), three modes ----------------
// mode 0: store RAW logits to out + accumulate rowsums   (regions 0,1 pass 1)
// mode 1: rowsums only, no store                          (regions 2,3 pass 1)
// mode 2: store FINAL (logit - SUB), no rowsums           (regions 2,3 pass 2)
// block: 64 rows x 128 cols, 8 warps (2M x 4N), warp tile 32x32.
__global__ void k_logits(const float* __restrict__ W, const float* __restrict__ b,
                         float* __restrict__ out,
                         int N, int K, int yofs, int colBase, int region, int mode) {
    extern __shared__ char smem_raw[];
    __nv_bfloat16* As = (__nv_bfloat16*)smem_raw;
    // row stride in 4B words must be == 12 (mod 32) for conflict-free mma A loads
    const int LDA = ((K >> 6) << 6) + 24;

    const int tid  = threadIdx.x;
    const int lane = tid & 31, wid = tid >> 5;
    const int mBlk = blockIdx.x * 64;
    const int nBlk = blockIdx.y * 128;

    // ---- stage A tile (64 x K bf16) ----
    {
        const int cpr = K >> 3;  // uint4 chunks per row
        for (int r = wid * 8; r < wid * 8 + 8; r++) {
            const uint4* src = (const uint4*)(g_Yh + (size_t)(mBlk + r) * YSTRIDE + yofs);
            uint4* dst = (uint4*)(As + r * LDA);
            for (int c = lane; c < cpr; c += 32) dst[c] = src[c];
        }
    }
    __syncthreads();

    const int wm  = wid & 1;      // M warp
    const int wn  = wid >> 1;     // N warp
    const int qr  = lane >> 2;    // 0..7
    const int qc2 = (lane & 3) * 2;

    float acc[2][4][4];
#pragma unroll
    for (int mt = 0; mt < 2; mt++)
#pragma unroll
        for (int nt = 0; nt < 4; nt++)
#pragma unroll
            for (int c = 0; c < 4; c++) acc[mt][nt][c] = 0.f;

    int  nIdx[4];
    bool nValid[4];
#pragma unroll
    for (int nt = 0; nt < 4; nt++) {
        nIdx[nt]   = nBlk + wn * 32 + nt * 8 + qr;
        nValid[nt] = nIdx[nt] < N;
    }

    const int NK = K >> 4;
    float2 fB[4][2];
#pragma unroll
    for (int nt = 0; nt < 4; nt++) {
        if (nValid[nt]) {
            const float* wp = W + (size_t)nIdx[nt] * K + qc2;
            fB[nt][0] = *(const float2*)(wp);
            fB[nt][1] = *(const float2*)(wp + 8);
        } else {
            fB[nt][0] = make_float2(0.f, 0.f);
            fB[nt][1] = make_float2(0.f, 0.f);
        }
    }

    for (int ks = 0; ks < NK; ks++) {
        const int k0 = ks * 16;
        float2 nxt[4][2];
        if (ks + 1 < NK) {
#pragma unroll
            for (int nt = 0; nt < 4; nt++) {
                if (nValid[nt]) {
                    const float* wp = W + (size_t)nIdx[nt] * K + k0 + 16 + qc2;
                    nxt[nt][0] = *(const float2*)(wp);
                    nxt[nt][1] = *(const float2*)(wp + 8);
                } else {
                    nxt[nt][0] = make_float2(0.f, 0.f);
                    nxt[nt][1] = make_float2(0.f, 0.f);
                }
            }
        }

        uint32_t a[2][4];
#pragma unroll
        for (int mt = 0; mt < 2; mt++) {
            const __nv_bfloat16* ap = As + (wm * 32 + mt * 16 + qr) * LDA + k0 + qc2;
            a[mt][0] = *(const uint32_t*)(ap);
            a[mt][1] = *(const uint32_t*)(ap + 8 * LDA);
            a[mt][2] = *(const uint32_t*)(ap + 8);
            a[mt][3] = *(const uint32_t*)(ap + 8 * LDA + 8);
        }

        uint32_t bfr[4][2];
#pragma unroll
        for (int nt = 0; nt < 4; nt++)
#pragma unroll
            for (int h = 0; h < 2; h++) {
                __nv_bfloat162 hv = __floats2bfloat162_rn(fB[nt][h].x, fB[nt][h].y);
                bfr[nt][h] = *reinterpret_cast<uint32_t*>(&hv);
            }

#pragma unroll
        for (int mt = 0; mt < 2; mt++)
#pragma unroll
            for (int nt = 0; nt < 4; nt++) {
                asm volatile(
                    "mma.sync.aligned.m16n8k16.row.col.f32.bf16.bf16.f32 "
                    "{%0,%1,%2,%3}, {%4,%5,%6,%7}, {%8,%9}, {%0,%1,%2,%3};\n"
                    : "+f"(acc[mt][nt][0]), "+f"(acc[mt][nt][1]),
                      "+f"(acc[mt][nt][2]), "+f"(acc[mt][nt][3])
                    : "r"(a[mt][0]), "r"(a[mt][1]), "r"(a[mt][2]), "r"(a[mt][3]),
                      "r"(bfr[nt][0]), "r"(bfr[nt][1]));
            }

        if (ks + 1 < NK) {
#pragma unroll
            for (int nt = 0; nt < 4; nt++) {
                fB[nt][0] = nxt[nt][0];
                fB[nt][1] = nxt[nt][1];
            }
        }
    }

    // ---- epilogue ----
    __syncthreads();

    if (mode == 2) {
        // final store: out = logit + bias - SUB[region][row]
#pragma unroll
        for (int mt = 0; mt < 2; mt++) {
#pragma unroll
            for (int hh = 0; hh < 2; hh++) {
                int rloc = wm * 32 + mt * 16 + qr + hh * 8;
                size_t rgl = (size_t)(mBlk + rloc);
                float sub = g_SUB[region * NROWS + rgl];
#pragma unroll
                for (int nt = 0; nt < 4; nt++) {
                    int n0 = nBlk + wn * 32 + nt * 8 + qc2;
#pragma unroll
                    for (int p = 0; p < 2; p++) {
                        int n = n0 + p;
                        if (n < N)
                            out[rgl * V_TOTAL + colBase + n] =
                                acc[mt][nt][hh * 2 + p] + b[n] - sub;
                    }
                }
            }
        }
        return;
    }

    // modes 0/1: per-row exp-sums (+ raw store if mode 0)
    float* srow = (float*)smem_raw;  // reuse smem
    if (tid < 64) srow[tid] = 0.f;
    __syncthreads();

#pragma unroll
    for (int mt = 0; mt < 2; mt++) {
#pragma unroll
        for (int hh = 0; hh < 2; hh++) {
            int rloc = wm * 32 + mt * 16 + qr + hh * 8;
            size_t rgl = (size_t)(mBlk + rloc);
            float part = 0.f;
#pragma unroll
            for (int nt = 0; nt < 4; nt++) {
                int n0 = nBlk + wn * 32 + nt * 8 + qc2;
#pragma unroll
                for (int p = 0; p < 2; p++) {
                    int n = n0 + p;
                    if (n < N) {
                        float v = acc[mt][nt][hh * 2 + p] + b[n];
                        if (mode == 0)
                            out[rgl * V_TOTAL + colBase + n] = v;
                        part += __expf(v);
                    }
                }
            }
            part += __shfl_xor_sync(0xffffffffu, part, 1);
            part += __shfl_xor_sync(0xffffffffu, part, 2);
            if ((lane & 3) == 0) atomicAdd(&srow[rloc], part);
        }
    }
    __syncthreads();
    if (tid < 64)
        atomicAdd(&g_rowsum[region * NROWS + mBlk + tid], srow[tid]);
}

// ---------------- K3: cluster logits + per-region subtract terms ----------------
__global__ void k_head_fix(const float* __restrict__ cw, const float* __restrict__ cb) {
    const int row = blockIdx.x;
    const int tid = threadIdx.x;  // 128
    __shared__ float red[3][128];
    float p0 = 0.f, p1 = 0.f, p2 = 0.f;
    const float* y = g_Yf + (size_t)row * YSTRIDE;  // y0, K=1024
    for (int e = tid; e < 1024; e += 128) {
        float yv = y[e];
        p0 += yv * cw[e];
        p1 += yv * cw[1024 + e];
        p2 += yv * cw[2048 + e];
    }
    red[0][tid] = p0; red[1][tid] = p1; red[2][tid] = p2;
    __syncthreads();
    for (int s = 64; s > 0; s >>= 1) {
        if (tid < s) {
            red[0][tid] += red[0][tid + s];
            red[1][tid] += red[1][tid + s];
            red[2][tid] += red[2][tid + s];
        }
        __syncthreads();
    }
    if (tid == 0) {
        float c0 = red[0][0] + cb[0];
        float c1 = red[1][0] + cb[1];
        float c2 = red[2][0] + cb[2];
        float s = g_rowsum[row] + __expf(c0) + __expf(c1) + __expf(c2);
        float lse0 = logf(s);
        g_SUB[row] = lse0;                       // head: out = logit - lse0
        float cl[3] = {c0 - lse0, c1 - lse0, c2 - lse0};
        for (int i = 1; i < 4; i++)              // tail: out = logit - lse_i + cl[i-1]
            g_SUB[i * NROWS + row] = logf(g_rowsum[i * NROWS + row]) - cl[i - 1];
    }
}

// ---------------- K4: subtract over regions 0/1 only (cols < 40000) ----------------
__global__ void k_sub01(float* __restrict__ out) {
    int i = blockIdx.x * blockDim.x + threadIdx.x;
    if (i >= NROWS * 40000) return;
    int row = i / 40000;
    int col = i - row * 40000;
    int reg = (col < 20000) ? 0 : 1;
    out[(size_t)row * V_TOTAL + col] -= g_SUB[reg * NROWS + row];
}

// ---------------- K5: loss = mean(-lp[target]) ----------------
__global__ void k_loss(const float* __restrict__ out, const int* __restrict__ tgt,
                       float* __restrict__ loss_out) {
    __shared__ float red[512];
    int r = threadIdx.x;
    int t = tgt[r];
    red[r] = -out[(size_t)r * V_TOTAL + t];
    __syncthreads();
    for (int s = 256; s > 0; s >>= 1) {
        if (r < s) red[r] += red[r + s];
        __syncthreads();
    }
    if (r == 0) *loss_out = red[0] / 512.f;
}

// ---------------- launch ----------------
extern "C" void kernel_launch(void* const* d_in, const int* in_sizes, int n_in,
                              void* d_out, int out_size) {
    const float* hidden = (const float*)d_in[0];
    const int*   target = (const int*)d_in[1];
    const float* cw     = (const float*)d_in[2];
    const float* cb     = (const float*)d_in[3];
    const float* W[4]  = {(const float*)d_in[4],  (const float*)d_in[7],
                          (const float*)d_in[10], (const float*)d_in[13]};
    const float* bb[4] = {(const float*)d_in[5],  (const float*)d_in[8],
                          (const float*)d_in[11], (const float*)d_in[14]};
    const float* P[4]  = {(const float*)d_in[6],  (const float*)d_in[9],
                          (const float*)d_in[12], (const float*)d_in[15]};
    float* out = (float*)d_out;

    static const int Ns[4]      = {20000, 20000, 160000, 67735};
    static const int Ks[4]      = {1024, 256, 64, 16};
    static const int yofs[4]    = {0, 1024, 1280, 1344};
    static const int colBase[4] = {0, 20000, 40000, 200000};

    auto smem_for = [](int K) { return 64 * (((K >> 6) << 6) + 24) * 2; };
    cudaFuncSetAttribute(k_logits, cudaFuncAttributeMaxDynamicSharedMemorySize,
                         smem_for(1024));

    k_zero<<<8, 256>>>();

    // all projections in one launch (22 ntiles x 8 mtiles = 176 blocks)
    k_proj_all<<<dim3(22, 8), 256>>>(hidden, P[0], P[1], P[2], P[3]);

    // pass 1: r0/r1 store raw + rowsum (mode 0); r2/r3 rowsum only (mode 1)
    for (int i = 0; i < 4; i++) {
        dim3 grid(8, (Ns[i] + 127) / 128);   // mtile fast-varying -> W reuse in L2
        int mode = (i < 2) ? 0 : 1;
        k_logits<<<grid, 256, smem_for(Ks[i])>>>(W[i], bb[i], out, Ns[i], Ks[i],
                                                 yofs[i], colBase[i], i, mode);
    }

    k_head_fix<<<512, 128>>>(cw, cb);

    // pass 2: subtract for r0/r1; recompute+final store for r2/r3 (mode 2)
    k_sub01<<<(NROWS * 40000 + 255) / 256, 256>>>(out);
    for (int i = 2; i < 4; i++) {
        dim3 grid(8, (Ns[i] + 127) / 128);
        k_logits<<<grid, 256, smem_for(Ks[i])>>>(W[i], bb[i], out, Ns[i], Ks[i],
                                                 yofs[i], colBase[i], i, 2);
    }

    k_loss<<<1, 512>>>(out, target, out + (size_t)out_size - 1);
}

// round 12
// speedup vs baseline: 1.2132x; 1.1209x over previous
#include <cuda_runtime.h>
#include <cuda_bf16.h>
#include <cstdint>

#define V_TOTAL 267735
#define NROWS   512
#define YSTRIDE 1360   // 1024 + 256 + 64 + 16
#define KC      256    // K-chunk staged in smem

// W bf16 scratch: 20000*1024 + 20000*256 + 160000*64 + 67735*16 = 36,923,760
#define WH_TOTAL 36923760

// ---------------- device scratch (no allocations allowed) ----------------
__device__ float          g_Yf[NROWS * YSTRIDE];   // fp32 projections (head cluster)
__device__ __nv_bfloat16  g_Yh[NROWS * YSTRIDE];   // bf16 projections (GEMM A)
__device__ __nv_bfloat16  g_Wh[WH_TOTAL];          // bf16 weights (GEMM B)
__device__ float          g_rowsum[4 * NROWS];     // sum(exp(logit)) per region/row
__device__ float          g_SUB[4 * NROWS];        // per-region per-row subtract term

// ---------------- K0: zero the row sums ----------------
__global__ void k_zero() {
    int i = blockIdx.x * blockDim.x + threadIdx.x;
    if (i < 4 * NROWS) g_rowsum[i] = 0.f;
}

// ---------------- K0b: convert all W to bf16 (float4 -> 4x bf16) ----------------
__global__ void k_cvtW(const float* __restrict__ W0, const float* __restrict__ W1,
                       const float* __restrict__ W2, const float* __restrict__ W3) {
    long i4 = (long)blockIdx.x * blockDim.x + threadIdx.x;
    const float* src; long base4;
    if      (i4 < 5120000L) { src = W0; base4 = 0L; }
    else if (i4 < 6400000L) { src = W1; base4 = 5120000L; }
    else if (i4 < 8960000L) { src = W2; base4 = 6400000L; }
    else if (i4 < 9230940L) { src = W3; base4 = 8960000L; }
    else return;
    float4 v = ((const float4*)src)[i4 - base4];
    __nv_bfloat162 h0 = __floats2bfloat162_rn(v.x, v.y);
    __nv_bfloat162 h1 = __floats2bfloat162_rn(v.z, v.w);
    uint2 u;
    u.x = *reinterpret_cast<uint32_t*>(&h0);
    u.y = *reinterpret_cast<uint32_t*>(&h1);
    ((uint2*)g_Wh)[i4] = u;
}

// ---------------- K1: ALL projections fused: Y = H(512x1024) @ Pcat^T ----
__global__ void k_proj_all(const float* __restrict__ H,
                           const float* __restrict__ P0, const float* __restrict__ P1,
                           const float* __restrict__ P2, const float* __restrict__ P3) {
    __shared__ float As[16][66];
    __shared__ float Bs[16][66];

    const int nt = blockIdx.x;
    const float* P; int E, yofs, n0;
    if (nt < 16)       { P = P0; E = 1024; yofs = 0;    n0 = nt * 64; }
    else if (nt < 20)  { P = P1; E = 256;  yofs = 1024; n0 = (nt - 16) * 64; }
    else if (nt == 20) { P = P2; E = 64;   yofs = 1280; n0 = 0; }
    else               { P = P3; E = 16;   yofs = 1344; n0 = 0; }

    const int tid = threadIdx.x;
    const int tx = tid & 15, ty = tid >> 4;
    const int m0 = blockIdx.y * 64;

    float acc[4][4];
#pragma unroll
    for (int i = 0; i < 4; i++)
#pragma unroll
        for (int j = 0; j < 4; j++) acc[i][j] = 0.f;

    for (int k0 = 0; k0 < 1024; k0 += 16) {
#pragma unroll
        for (int i = 0; i < 4; i++) {
            int e = tid + i * 256;
            int r = e >> 4, c = e & 15;
            As[c][r] = H[(size_t)(m0 + r) * 1024 + k0 + c];
            int nn = n0 + r;
            Bs[c][r] = (nn < E) ? P[(size_t)nn * 1024 + k0 + c] : 0.f;
        }
        __syncthreads();
#pragma unroll
        for (int k = 0; k < 16; k++) {
            float am[4], bn[4];
#pragma unroll
            for (int i = 0; i < 4; i++) am[i] = As[k][ty * 4 + i];
#pragma unroll
            for (int j = 0; j < 4; j++) bn[j] = Bs[k][tx * 4 + j];
#pragma unroll
            for (int i = 0; i < 4; i++)
#pragma unroll
                for (int j = 0; j < 4; j++) acc[i][j] += am[i] * bn[j];
        }
        __syncthreads();
    }
#pragma unroll
    for (int i = 0; i < 4; i++) {
        int m = m0 + ty * 4 + i;
#pragma unroll
        for (int j = 0; j < 4; j++) {
            int n = n0 + tx * 4 + j;
            if (n < E) {
                size_t idx = (size_t)m * YSTRIDE + yofs + n;
                g_Yf[idx] = acc[i][j];
                g_Yh[idx] = __float2bfloat16(acc[i][j]);
            }
        }
    }
}

// ---------------- K2: logits GEMM (bf16 mma), K-chunked, multi-n-tile ----------
// mode 0: store RAW logits + rowsums   (r0/r1 pass 1)
// mode 1: rowsums only                 (r2/r3 pass 1)
// mode 2: store FINAL logit - SUB      (r2/r3 pass 2)
// block: 64 rows x 128 cols per tile, ntPerBlk tiles along N.
__global__ __launch_bounds__(256, 3)
void k_logits(const __nv_bfloat16* __restrict__ W, const float* __restrict__ b,
              float* __restrict__ out,
              int N, int K, int yofs, int colBase, int region, int mode,
              int ntPerBlk) {
    extern __shared__ char smem_raw[];
    __nv_bfloat16* As = (__nv_bfloat16*)smem_raw;
    const int kc  = (K < KC) ? K : KC;
    // row stride in bf16 elems == 24 (mod 64) -> 12 (mod 32) words: conflict-free
    const int LDA = ((kc >> 6) << 6) + 24;
    float* srow = (float*)(smem_raw + (size_t)64 * LDA * 2);

    const int tid  = threadIdx.x;
    const int lane = tid & 31, wid = tid >> 5;
    const int mBlk = blockIdx.x * 64;

    const int wm  = wid & 1;
    const int wn  = wid >> 1;
    const int qr  = lane >> 2;
    const int qc2 = (lane & 3) * 2;

    for (int t = 0; t < ntPerBlk; t++) {
        const int nBlk = (blockIdx.y * ntPerBlk + t) * 128;
        if (nBlk >= N) break;   // uniform across block

        int  nIdx[4];
        bool nValid[4];
#pragma unroll
        for (int nt = 0; nt < 4; nt++) {
            nIdx[nt]   = nBlk + wn * 32 + nt * 8 + qr;
            nValid[nt] = nIdx[nt] < N;
        }

        float acc[2][4][4];
#pragma unroll
        for (int mt = 0; mt < 2; mt++)
#pragma unroll
            for (int nt = 0; nt < 4; nt++)
#pragma unroll
                for (int c = 0; c < 4; c++) acc[mt][nt][c] = 0.f;

        for (int kc0 = 0; kc0 < K; kc0 += kc) {
            if (K > kc || t == 0) {   // restage only when needed (uniform)
                __syncthreads();
                const int cpr = kc >> 3;
                for (int r = wid * 8; r < wid * 8 + 8; r++) {
                    const uint4* src =
                        (const uint4*)(g_Yh + (size_t)(mBlk + r) * YSTRIDE + yofs + kc0);
                    uint4* dst = (uint4*)(As + r * LDA);
                    for (int c = lane; c < cpr; c += 32) dst[c] = src[c];
                }
                __syncthreads();
            }

            const int nk = kc >> 4;
            uint32_t fB[4][2];
#pragma unroll
            for (int nt = 0; nt < 4; nt++) {
                if (nValid[nt]) {
                    const __nv_bfloat16* wp = W + (size_t)nIdx[nt] * K + kc0 + qc2;
                    fB[nt][0] = *(const uint32_t*)(wp);
                    fB[nt][1] = *(const uint32_t*)(wp + 8);
                } else { fB[nt][0] = 0u; fB[nt][1] = 0u; }
            }

            for (int ks = 0; ks < nk; ks++) {
                const int k0 = ks * 16;
                uint32_t nxt[4][2];
                if (ks + 1 < nk) {
#pragma unroll
                    for (int nt = 0; nt < 4; nt++) {
                        if (nValid[nt]) {
                            const __nv_bfloat16* wp =
                                W + (size_t)nIdx[nt] * K + kc0 + k0 + 16 + qc2;
                            nxt[nt][0] = *(const uint32_t*)(wp);
                            nxt[nt][1] = *(const uint32_t*)(wp + 8);
                        } else { nxt[nt][0] = 0u; nxt[nt][1] = 0u; }
                    }
                }

                uint32_t a[2][4];
#pragma unroll
                for (int mt = 0; mt < 2; mt++) {
                    const __nv_bfloat16* ap =
                        As + (wm * 32 + mt * 16 + qr) * LDA + k0 + qc2;
                    a[mt][0] = *(const uint32_t*)(ap);
                    a[mt][1] = *(const uint32_t*)(ap + 8 * LDA);
                    a[mt][2] = *(const uint32_t*)(ap + 8);
                    a[mt][3] = *(const uint32_t*)(ap + 8 * LDA + 8);
                }

#pragma unroll
                for (int mt = 0; mt < 2; mt++)
#pragma unroll
                    for (int nt = 0; nt < 4; nt++) {
                        asm volatile(
                            "mma.sync.aligned.m16n8k16.row.col.f32.bf16.bf16.f32 "
                            "{%0,%1,%2,%3}, {%4,%5,%6,%7}, {%8,%9}, {%0,%1,%2,%3};\n"
                            : "+f"(acc[mt][nt][0]), "+f"(acc[mt][nt][1]),
                              "+f"(acc[mt][nt][2]), "+f"(acc[mt][nt][3])
                            : "r"(a[mt][0]), "r"(a[mt][1]), "r"(a[mt][2]), "r"(a[mt][3]),
                              "r"(fB[nt][0]), "r"(fB[nt][1]));
                    }

                if (ks + 1 < nk) {
#pragma unroll
                    for (int nt = 0; nt < 4; nt++) {
                        fB[nt][0] = nxt[nt][0];
                        fB[nt][1] = nxt[nt][1];
                    }
                }
            }
        }

        // ---- epilogue for this tile ----
        if (mode == 2) {
#pragma unroll
            for (int mt = 0; mt < 2; mt++) {
#pragma unroll
                for (int hh = 0; hh < 2; hh++) {
                    int rloc = wm * 32 + mt * 16 + qr + hh * 8;
                    size_t rgl = (size_t)(mBlk + rloc);
                    float sub = g_SUB[region * NROWS + rgl];
#pragma unroll
                    for (int nt = 0; nt < 4; nt++) {
                        int n0 = nBlk + wn * 32 + nt * 8 + qc2;
#pragma unroll
                        for (int p = 0; p < 2; p++) {
                            int n = n0 + p;
                            if (n < N)
                                out[rgl * V_TOTAL + colBase + n] =
                                    acc[mt][nt][hh * 2 + p] + b[n] - sub;
                        }
                    }
                }
            }
        } else {
            __syncthreads();
            if (tid < 64) srow[tid] = 0.f;
            __syncthreads();
#pragma unroll
            for (int mt = 0; mt < 2; mt++) {
#pragma unroll
                for (int hh = 0; hh < 2; hh++) {
                    int rloc = wm * 32 + mt * 16 + qr + hh * 8;
                    size_t rgl = (size_t)(mBlk + rloc);
                    float part = 0.f;
#pragma unroll
                    for (int nt = 0; nt < 4; nt++) {
                        int n0 = nBlk + wn * 32 + nt * 8 + qc2;
#pragma unroll
                        for (int p = 0; p < 2; p++) {
                            int n = n0 + p;
                            if (n < N) {
                                float v = acc[mt][nt][hh * 2 + p] + b[n];
                                if (mode == 0)
                                    out[rgl * V_TOTAL + colBase + n] = v;
                                part += __expf(v);
                            }
                        }
                    }
                    part += __shfl_xor_sync(0xffffffffu, part, 1);
                    part += __shfl_xor_sync(0xffffffffu, part, 2);
                    if ((lane & 3) == 0) atomicAdd(&srow[rloc], part);
                }
            }
            __syncthreads();
            if (tid < 64)
                atomicAdd(&g_rowsum[region * NROWS + mBlk + tid], srow[tid]);
        }
    }
}

// ---------------- K3: cluster logits + per-region subtract terms ----------------
__global__ void k_head_fix(const float* __restrict__ cw, const float* __restrict__ cb) {
    const int row = blockIdx.x;
    const int tid = threadIdx.x;  // 128
    __shared__ float red[3][128];
    float p0 = 0.f, p1 = 0.f, p2 = 0.f;
    const float* y = g_Yf + (size_t)row * YSTRIDE;
    for (int e = tid; e < 1024; e += 128) {
        float yv = y[e];
        p0 += yv * cw[e];
        p1 += yv * cw[1024 + e];
        p2 += yv * cw[2048 + e];
    }
    red[0][tid] = p0; red[1][tid] = p1; red[2][tid] = p2;
    __syncthreads();
    for (int s = 64; s > 0; s >>= 1) {
        if (tid < s) {
            red[0][tid] += red[0][tid + s];
            red[1][tid] += red[1][tid + s];
            red[2][tid] += red[2][tid + s];
        }
        __syncthreads();
    }
    if (tid == 0) {
        float c0 = red[0][0] + cb[0];
        float c1 = red[1][0] + cb[1];
        float c2 = red[2][0] + cb[2];
        float s = g_rowsum[row] + __expf(c0) + __expf(c1) + __expf(c2);
        float lse0 = logf(s);
        g_SUB[row] = lse0;
        float cl[3] = {c0 - lse0, c1 - lse0, c2 - lse0};
        for (int i = 1; i < 4; i++)
            g_SUB[i * NROWS + row] = logf(g_rowsum[i * NROWS + row]) - cl[i - 1];
    }
}

// ---------------- K4: subtract over regions 0/1 only (cols < 40000) ----------------
__global__ void k_sub01(float* __restrict__ out) {
    int i = blockIdx.x * blockDim.x + threadIdx.x;
    if (i >= NROWS * 40000) return;
    int row = i / 40000;
    int col = i - row * 40000;
    int reg = (col < 20000) ? 0 : 1;
    out[(size_t)row * V_TOTAL + col] -= g_SUB[reg * NROWS + row];
}

// ---------------- K5: loss = mean(-lp[target]) ----------------
__global__ void k_loss(const float* __restrict__ out, const int* __restrict__ tgt,
                       float* __restrict__ loss_out) {
    __shared__ float red[512];
    int r = threadIdx.x;
    int t = tgt[r];
    red[r] = -out[(size_t)r * V_TOTAL + t];
    __syncthreads();
    for (int s = 256; s > 0; s >>= 1) {
        if (r < s) red[r] += red[r + s];
        __syncthreads();
    }
    if (r == 0) *loss_out = red[0] / 512.f;
}

// ---------------- launch ----------------
extern "C" void kernel_launch(void* const* d_in, const int* in_sizes, int n_in,
                              void* d_out, int out_size) {
    const float* hidden = (const float*)d_in[0];
    const int*   target = (const int*)d_in[1];
    const float* cw     = (const float*)d_in[2];
    const float* cb     = (const float*)d_in[3];
    const float* W[4]  = {(const float*)d_in[4],  (const float*)d_in[7],
                          (const float*)d_in[10], (const float*)d_in[13]};
    const float* bb[4] = {(const float*)d_in[5],  (const float*)d_in[8],
                          (const float*)d_in[11], (const float*)d_in[14]};
    const float* P[4]  = {(const float*)d_in[6],  (const float*)d_in[9],
                          (const float*)d_in[12], (const float*)d_in[15]};
    float* out = (float*)d_out;

    static const int  Ns[4]      = {20000, 20000, 160000, 67735};
    static const int  Ks[4]      = {1024, 256, 64, 16};
    static const int  yofs[4]    = {0, 1024, 1280, 1344};
    static const int  colBase[4] = {0, 20000, 40000, 200000};
    static const long wofs[4]    = {0L, 20480000L, 25600000L, 35840000L};
    static const int  NT[4]      = {4, 4, 8, 8};

    auto smem_for = [](int K) {
        int kc = (K < KC) ? K : KC;
        int LDA = ((kc >> 6) << 6) + 24;
        return 64 * LDA * 2 + 256;
    };
    cudaFuncSetAttribute(k_logits, cudaFuncAttributeMaxDynamicSharedMemorySize,
                         smem_for(1024));

    k_zero<<<8, 256>>>();
    k_cvtW<<<(9230940 + 255) / 256, 256>>>(W[0], W[1], W[2], W[3]);
    k_proj_all<<<dim3(22, 8), 256>>>(hidden, P[0], P[1], P[2], P[3]);

    // resolve g_Wh device address for pointer arithmetic on host
    __nv_bfloat16* whBase = nullptr;
    cudaGetSymbolAddress((void**)&whBase, g_Wh);

    // pass 1: r0/r1 raw store + rowsum (mode 0); r2/r3 rowsum only (mode 1)
    for (int i = 0; i < 4; i++) {
        int ntiles = (Ns[i] + 127) / 128;
        dim3 grid(8, (ntiles + NT[i] - 1) / NT[i]);
        int mode = (i < 2) ? 0 : 1;
        k_logits<<<grid, 256, smem_for(Ks[i])>>>(whBase + wofs[i], bb[i], out,
                                                 Ns[i], Ks[i], yofs[i],
                                                 colBase[i], i, mode, NT[i]);
    }

    k_head_fix<<<512, 128>>>(cw, cb);

    // pass 2: subtract r0/r1; recompute + final store r2/r3
    k_sub01<<<(NROWS * 40000 + 255) / 256, 256>>>(out);
    for (int i = 2; i < 4; i++) {
        int ntiles = (Ns[i] + 127) / 128;
        dim3 grid(8, (ntiles + NT[i] - 1) / NT[i]);
        k_logits<<<grid, 256, smem_for(Ks[i])>>>(whBase + wofs[i], bb[i], out,
                                                 Ns[i], Ks[i], yofs[i],
                                                 colBase[i], i, 2, NT[i]);
    }

    k_loss<<<1, 512>>>(out, target, out + (size_t)out_size - 1);
}

// round 13
// speedup vs baseline: 1.4438x; 1.1901x over previous
#include <cuda_runtime.h>
#include <cuda_bf16.h>
#include <cstdint>

#define V_TOTAL 267735
#define NROWS   512
#define YSTRIDE 1360   // 1024 + 256 + 64 + 16
#define KC      256    // K-chunk staged in smem

// W bf16 scratch: 20000*1024 + 20000*256 + 160000*64 + 67735*16 = 36,923,760
#define WH_TOTAL 36923760

// ---------------- device scratch (no allocations allowed) ----------------
__device__ float          g_Yf[NROWS * YSTRIDE];   // fp32 projections (head cluster)
__device__ __nv_bfloat16  g_Yh[NROWS * YSTRIDE];   // bf16 projections (GEMM A)
__device__ __nv_bfloat16  g_Wh[WH_TOTAL];          // bf16 weights (GEMM B)
__device__ float          g_rowsum[4 * NROWS];     // sum(exp(logit)) per region/row
__device__ float          g_SUB[4 * NROWS];        // per-region per-row subtract term

// ---------------- K0: zero the row sums ----------------
__global__ void k_zero() {
    int i = blockIdx.x * blockDim.x + threadIdx.x;
    if (i < 4 * NROWS) g_rowsum[i] = 0.f;
}

// ---------------- K0b: convert all W to bf16 (float4 -> 4x bf16) ----------------
__global__ void k_cvtW(const float* __restrict__ W0, const float* __restrict__ W1,
                       const float* __restrict__ W2, const float* __restrict__ W3) {
    long i4 = (long)blockIdx.x * blockDim.x + threadIdx.x;
    const float* src; long base4;
    if      (i4 < 5120000L) { src = W0; base4 = 0L; }
    else if (i4 < 6400000L) { src = W1; base4 = 5120000L; }
    else if (i4 < 8960000L) { src = W2; base4 = 6400000L; }
    else if (i4 < 9230940L) { src = W3; base4 = 8960000L; }
    else return;
    float4 v = ((const float4*)src)[i4 - base4];
    __nv_bfloat162 h0 = __floats2bfloat162_rn(v.x, v.y);
    __nv_bfloat162 h1 = __floats2bfloat162_rn(v.z, v.w);
    uint2 u;
    u.x = *reinterpret_cast<uint32_t*>(&h0);
    u.y = *reinterpret_cast<uint32_t*>(&h1);
    ((uint2*)g_Wh)[i4] = u;
}

// ---------------- K1: ALL projections fused: Y = H(512x1024) @ Pcat^T ----
__global__ void k_proj_all(const float* __restrict__ H,
                           const float* __restrict__ P0, const float* __restrict__ P1,
                           const float* __restrict__ P2, const float* __restrict__ P3) {
    __shared__ float As[16][66];
    __shared__ float Bs[16][66];

    const int nt = blockIdx.x;
    const float* P; int E, yofs, n0;
    if (nt < 16)       { P = P0; E = 1024; yofs = 0;    n0 = nt * 64; }
    else if (nt < 20)  { P = P1; E = 256;  yofs = 1024; n0 = (nt - 16) * 64; }
    else if (nt == 20) { P = P2; E = 64;   yofs = 1280; n0 = 0; }
    else               { P = P3; E = 16;   yofs = 1344; n0 = 0; }

    const int tid = threadIdx.x;
    const int tx = tid & 15, ty = tid >> 4;
    const int m0 = blockIdx.y * 64;

    float acc[4][4];
#pragma unroll
    for (int i = 0; i < 4; i++)
#pragma unroll
        for (int j = 0; j < 4; j++) acc[i][j] = 0.f;

    for (int k0 = 0; k0 < 1024; k0 += 16) {
#pragma unroll
        for (int i = 0; i < 4; i++) {
            int e = tid + i * 256;
            int r = e >> 4, c = e & 15;
            As[c][r] = H[(size_t)(m0 + r) * 1024 + k0 + c];
            int nn = n0 + r;
            Bs[c][r] = (nn < E) ? P[(size_t)nn * 1024 + k0 + c] : 0.f;
        }
        __syncthreads();
#pragma unroll
        for (int k = 0; k < 16; k++) {
            float am[4], bn[4];
#pragma unroll
            for (int i = 0; i < 4; i++) am[i] = As[k][ty * 4 + i];
#pragma unroll
            for (int j = 0; j < 4; j++) bn[j] = Bs[k][tx * 4 + j];
#pragma unroll
            for (int i = 0; i < 4; i++)
#pragma unroll
                for (int j = 0; j < 4; j++) acc[i][j] += am[i] * bn[j];
        }
        __syncthreads();
    }
#pragma unroll
    for (int i = 0; i < 4; i++) {
        int m = m0 + ty * 4 + i;
#pragma unroll
        for (int j = 0; j < 4; j++) {
            int n = n0 + tx * 4 + j;
            if (n < E) {
                size_t idx = (size_t)m * YSTRIDE + yofs + n;
                g_Yf[idx] = acc[i][j];
                g_Yh[idx] = __float2bfloat16(acc[i][j]);
            }
        }
    }
}

// ---------------- K2: logits GEMM (bf16 mma), K-chunked, multi-n-tile ----------
// Block tile 64 rows x 256 cols; 8 warps, each warp 64 rows x 32 UNIQUE cols
// (no duplicated B loads). A fragments via ldmatrix.x4 from smem.
// mode 0: store RAW logits + rowsums   (r0/r1 pass 1)
// mode 1: rowsums only                 (r2/r3 pass 1)
// mode 2: store FINAL logit - SUB      (r2/r3 pass 2)
__global__ __launch_bounds__(256, 2)
void k_logits(const __nv_bfloat16* __restrict__ W, const float* __restrict__ b,
              float* __restrict__ out,
              int N, int K, int yofs, int colBase, int region, int mode,
              int ntPerBlk) {
    extern __shared__ char smem_raw[];
    __nv_bfloat16* As = (__nv_bfloat16*)smem_raw;
    const int kc  = (K < KC) ? K : KC;
    // row stride in bf16: == 24 (mod 64) -> 12 words (mod 32): conflict-free
    // for both LDSM 8-row phases and the staging stores.
    const int LDA = ((kc >> 6) << 6) + 24;
    float* srow = (float*)(smem_raw + (size_t)64 * LDA * 2);

    const int tid  = threadIdx.x;
    const int lane = tid & 31, wid = tid >> 5;
    const int mBlk = blockIdx.x * 64;

    const int qr  = lane >> 2;       // 0..7
    const int qc2 = (lane & 3) * 2;  // 0,2,4,6

    // per-lane ldmatrix base: row = (lane&15), k-half = (lane>>4)*8
    uint32_t smemA = (uint32_t)__cvta_generic_to_shared(As);
    const uint32_t aLane = smemA +
        (uint32_t)(((lane & 15) * LDA + ((lane >> 4) << 3)) * 2);

    for (int t = 0; t < ntPerBlk; t++) {
        const int nBlk = (blockIdx.y * ntPerBlk + t) * 256;
        if (nBlk >= N) break;   // uniform across block

        int  nIdx[4];
        bool nValid[4];
#pragma unroll
        for (int nt = 0; nt < 4; nt++) {
            nIdx[nt]   = nBlk + wid * 32 + nt * 8 + qr;
            nValid[nt] = nIdx[nt] < N;
        }

        float acc[4][4][4];   // [mt 16-row][nt 8-col][c]
#pragma unroll
        for (int mt = 0; mt < 4; mt++)
#pragma unroll
            for (int nt = 0; nt < 4; nt++)
#pragma unroll
                for (int c = 0; c < 4; c++) acc[mt][nt][c] = 0.f;

        for (int kc0 = 0; kc0 < K; kc0 += kc) {
            if (K > kc || t == 0) {   // restage only when needed (uniform)
                __syncthreads();
                const int cpr = kc >> 3;
                for (int r = wid * 8; r < wid * 8 + 8; r++) {
                    const uint4* src =
                        (const uint4*)(g_Yh + (size_t)(mBlk + r) * YSTRIDE + yofs + kc0);
                    uint4* dst = (uint4*)(As + r * LDA);
                    for (int c = lane; c < cpr; c += 32) dst[c] = src[c];
                }
                __syncthreads();
            }

            const int nk = kc >> 4;
            uint32_t fB[4][2];
#pragma unroll
            for (int nt = 0; nt < 4; nt++) {
                if (nValid[nt]) {
                    const __nv_bfloat16* wp = W + (size_t)nIdx[nt] * K + kc0 + qc2;
                    fB[nt][0] = *(const uint32_t*)(wp);
                    fB[nt][1] = *(const uint32_t*)(wp + 8);
                } else { fB[nt][0] = 0u; fB[nt][1] = 0u; }
            }

            for (int ks = 0; ks < nk; ks++) {
                const int k0 = ks * 16;
                uint32_t nxt[4][2];
                if (ks + 1 < nk) {
#pragma unroll
                    for (int nt = 0; nt < 4; nt++) {
                        if (nValid[nt]) {
                            const __nv_bfloat16* wp =
                                W + (size_t)nIdx[nt] * K + kc0 + k0 + 16 + qc2;
                            nxt[nt][0] = *(const uint32_t*)(wp);
                            nxt[nt][1] = *(const uint32_t*)(wp + 8);
                        } else { nxt[nt][0] = 0u; nxt[nt][1] = 0u; }
                    }
                }

                // A fragments: one ldmatrix.x4 per 16-row tile
                uint32_t a[4][4];
#pragma unroll
                for (int mt = 0; mt < 4; mt++) {
                    uint32_t addr = aLane + (uint32_t)((mt * 16 * LDA + k0) * 2);
                    asm volatile(
                        "ldmatrix.sync.aligned.m8n8.x4.shared.b16 "
                        "{%0,%1,%2,%3}, [%4];"
                        : "=r"(a[mt][0]), "=r"(a[mt][1]),
                          "=r"(a[mt][2]), "=r"(a[mt][3])
                        : "r"(addr));
                }

#pragma unroll
                for (int mt = 0; mt < 4; mt++)
#pragma unroll
                    for (int nt = 0; nt < 4; nt++) {
                        asm volatile(
                            "mma.sync.aligned.m16n8k16.row.col.f32.bf16.bf16.f32 "
                            "{%0,%1,%2,%3}, {%4,%5,%6,%7}, {%8,%9}, {%0,%1,%2,%3};\n"
                            : "+f"(acc[mt][nt][0]), "+f"(acc[mt][nt][1]),
                              "+f"(acc[mt][nt][2]), "+f"(acc[mt][nt][3])
                            : "r"(a[mt][0]), "r"(a[mt][1]), "r"(a[mt][2]), "r"(a[mt][3]),
                              "r"(fB[nt][0]), "r"(fB[nt][1]));
                    }

                if (ks + 1 < nk) {
#pragma unroll
                    for (int nt = 0; nt < 4; nt++) {
                        fB[nt][0] = nxt[nt][0];
                        fB[nt][1] = nxt[nt][1];
                    }
                }
            }
        }

        // ---- epilogue for this tile ----
        if (mode == 2) {
#pragma unroll
            for (int mt = 0; mt < 4; mt++) {
#pragma unroll
                for (int hh = 0; hh < 2; hh++) {
                    int rloc = mt * 16 + qr + hh * 8;
                    size_t rgl = (size_t)(mBlk + rloc);
                    float sub = g_SUB[region * NROWS + rgl];
#pragma unroll
                    for (int nt = 0; nt < 4; nt++) {
                        int n0 = nBlk + wid * 32 + nt * 8 + qc2;
#pragma unroll
                        for (int p = 0; p < 2; p++) {
                            int n = n0 + p;
                            if (n < N)
                                out[rgl * V_TOTAL + colBase + n] =
                                    acc[mt][nt][hh * 2 + p] + b[n] - sub;
                        }
                    }
                }
            }
        } else {
            __syncthreads();
            if (tid < 64) srow[tid] = 0.f;
            __syncthreads();
#pragma unroll
            for (int mt = 0; mt < 4; mt++) {
#pragma unroll
                for (int hh = 0; hh < 2; hh++) {
                    int rloc = mt * 16 + qr + hh * 8;
                    size_t rgl = (size_t)(mBlk + rloc);
                    float part = 0.f;
#pragma unroll
                    for (int nt = 0; nt < 4; nt++) {
                        int n0 = nBlk + wid * 32 + nt * 8 + qc2;
#pragma unroll
                        for (int p = 0; p < 2; p++) {
                            int n = n0 + p;
                            if (n < N) {
                                float v = acc[mt][nt][hh * 2 + p] + b[n];
                                if (mode == 0)
                                    out[rgl * V_TOTAL + colBase + n] = v;
                                part += __expf(v);
                            }
                        }
                    }
                    part += __shfl_xor_sync(0xffffffffu, part, 1);
                    part += __shfl_xor_sync(0xffffffffu, part, 2);
                    if ((lane & 3) == 0) atomicAdd(&srow[rloc], part);
                }
            }
            __syncthreads();
            if (tid < 64)
                atomicAdd(&g_rowsum[region * NROWS + mBlk + tid], srow[tid]);
        }
    }
}

// ---------------- K3: cluster logits + per-region subtract terms ----------------
__global__ void k_head_fix(const float* __restrict__ cw, const float* __restrict__ cb) {
    const int row = blockIdx.x;
    const int tid = threadIdx.x;  // 128
    __shared__ float red[3][128];
    float p0 = 0.f, p1 = 0.f, p2 = 0.f;
    const float* y = g_Yf + (size_t)row * YSTRIDE;
    for (int e = tid; e < 1024; e += 128) {
        float yv = y[e];
        p0 += yv * cw[e];
        p1 += yv * cw[1024 + e];
        p2 += yv * cw[2048 + e];
    }
    red[0][tid] = p0; red[1][tid] = p1; red[2][tid] = p2;
    __syncthreads();
    for (int s = 64; s > 0; s >>= 1) {
        if (tid < s) {
            red[0][tid] += red[0][tid + s];
            red[1][tid] += red[1][tid + s];
            red[2][tid] += red[2][tid + s];
        }
        __syncthreads();
    }
    if (tid == 0) {
        float c0 = red[0][0] + cb[0];
        float c1 = red[1][0] + cb[1];
        float c2 = red[2][0] + cb[2];
        float s = g_rowsum[row] + __expf(c0) + __expf(c1) + __expf(c2);
        float lse0 = logf(s);
        g_SUB[row] = lse0;
        float cl[3] = {c0 - lse0, c1 - lse0, c2 - lse0};
        for (int i = 1; i < 4; i++)
            g_SUB[i * NROWS + row] = logf(g_rowsum[i * NROWS + row]) - cl[i - 1];
    }
}

// ---------------- K4: subtract over regions 0/1 only (cols < 40000) ----------------
__global__ void k_sub01(float* __restrict__ out) {
    int i = blockIdx.x * blockDim.x + threadIdx.x;
    if (i >= NROWS * 40000) return;
    int row = i / 40000;
    int col = i - row * 40000;
    int reg = (col < 20000) ? 0 : 1;
    out[(size_t)row * V_TOTAL + col] -= g_SUB[reg * NROWS + row];
}

// ---------------- K5: loss = mean(-lp[target]) ----------------
__global__ void k_loss(const float* __restrict__ out, const int* __restrict__ tgt,
                       float* __restrict__ loss_out) {
    __shared__ float red[512];
    int r = threadIdx.x;
    int t = tgt[r];
    red[r] = -out[(size_t)r * V_TOTAL + t];
    __syncthreads();
    for (int s = 256; s > 0; s >>= 1) {
        if (r < s) red[r] += red[r + s];
        __syncthreads();
    }
    if (r == 0) *loss_out = red[0] / 512.f;
}

// ---------------- launch ----------------
extern "C" void kernel_launch(void* const* d_in, const int* in_sizes, int n_in,
                              void* d_out, int out_size) {
    const float* hidden = (const float*)d_in[0];
    const int*   target = (const int*)d_in[1];
    const float* cw     = (const float*)d_in[2];
    const float* cb     = (const float*)d_in[3];
    const float* W[4]  = {(const float*)d_in[4],  (const float*)d_in[7],
                          (const float*)d_in[10], (const float*)d_in[13]};
    const float* bb[4] = {(const float*)d_in[5],  (const float*)d_in[8],
                          (const float*)d_in[11], (const float*)d_in[14]};
    const float* P[4]  = {(const float*)d_in[6],  (const float*)d_in[9],
                          (const float*)d_in[12], (const float*)d_in[15]};
    float* out = (float*)d_out;

    static const int  Ns[4]      = {20000, 20000, 160000, 67735};
    static const int  Ks[4]      = {1024, 256, 64, 16};
    static const int  yofs[4]    = {0, 1024, 1280, 1344};
    static const int  colBase[4] = {0, 20000, 40000, 200000};
    static const long wofs[4]    = {0L, 20480000L, 25600000L, 35840000L};
    static const int  NT[4]      = {1, 1, 8, 4};   // 256-col tiles per block

    auto smem_for = [](int K) {
        int kc = (K < KC) ? K : KC;
        int LDA = ((kc >> 6) << 6) + 24;
        return 64 * LDA * 2 + 256;
    };
    cudaFuncSetAttribute(k_logits, cudaFuncAttributeMaxDynamicSharedMemorySize,
                         smem_for(1024));

    k_zero<<<8, 256>>>();
    k_cvtW<<<(9230940 + 255) / 256, 256>>>(W[0], W[1], W[2], W[3]);
    k_proj_all<<<dim3(22, 8), 256>>>(hidden, P[0], P[1], P[2], P[3]);

    // resolve g_Wh device address for pointer arithmetic on host
    __nv_bfloat16* whBase = nullptr;
    cudaGetSymbolAddress((void**)&whBase, g_Wh);

    // pass 1: r0/r1 raw store + rowsum (mode 0); r2/r3 rowsum only (mode 1)
    for (int i = 0; i < 4; i++) {
        int ntiles = (Ns[i] + 255) / 256;
        dim3 grid(8, (ntiles + NT[i] - 1) / NT[i]);
        int mode = (i < 2) ? 0 : 1;
        k_logits<<<grid, 256, smem_for(Ks[i])>>>(whBase + wofs[i], bb[i], out,
                                                 Ns[i], Ks[i], yofs[i],
                                                 colBase[i], i, mode, NT[i]);
    }

    k_head_fix<<<512, 128>>>(cw, cb);

    // pass 2: subtract r0/r1; recompute + final store r2/r3
    k_sub01<<<(NROWS * 40000 + 255) / 256, 256>>>(out);
    for (int i = 2; i < 4; i++) {
        int ntiles = (Ns[i] + 255) / 256;
        dim3 grid(8, (ntiles + NT[i] - 1) / NT[i]);
        k_logits<<<grid, 256, smem_for(Ks[i])>>>(whBase + wofs[i], bb[i], out,
                                                 Ns[i], Ks[i], yofs[i],
                                                 colBase[i], i, 2, NT[i]);
    }

    k_loss<<<1, 512>>>(out, target, out + (size_t)out_size - 1);
}

// round 14
// speedup vs baseline: 1.6537x; 1.1454x over previous
#include <cuda_runtime.h>
#include <cuda_bf16.h>
#include <cstdint>

#define V_TOTAL 267735
#define NROWS   512
#define YSTRIDE 1360   // 1024 + 256 + 64 + 16

// W bf16 scratch: 20000*1024 + 20000*256 + 160000*64 + 67735*16 = 36,923,760
#define WH_TOTAL 36923760

// k_logits smem geometry (kc <= 64)
#define LDA 72
#define LDB 72
#define ABYTES (64 * LDA * 2)          // 9216
#define BBYTES (256 * LDB * 2)         // 36864
#define STG    (ABYTES + BBYTES)       // 46080 per stage
#define LOGITS_SMEM (2 * STG + 256)    // double buffer + srow

// ---------------- device scratch (no allocations allowed) ----------------
__device__ float          g_Yf[NROWS * YSTRIDE];   // fp32 projections (head cluster)
__device__ __nv_bfloat16  g_Yh[NROWS * YSTRIDE];   // bf16 projections (GEMM A)
__device__ __nv_bfloat16  g_Wh[WH_TOTAL];          // bf16 weights (GEMM B)
__device__ float          g_rowsum[4 * NROWS];     // sum(exp(logit)) per region/row
__device__ float          g_SUB[4 * NROWS];        // per-region per-row subtract term

__device__ __forceinline__ void cp16(uint32_t dst, const void* src, int srcBytes) {
    asm volatile("cp.async.cg.shared.global [%0], [%1], 16, %2;\n"
                 :: "r"(dst), "l"(src), "r"(srcBytes));
}

// ---------------- K0: zero the row sums ----------------
__global__ void k_zero() {
    int i = blockIdx.x * blockDim.x + threadIdx.x;
    if (i < 4 * NROWS) g_rowsum[i] = 0.f;
}

// ---------------- K0b: convert all W to bf16 (float4 -> 4x bf16) ----------------
__global__ void k_cvtW(const float* __restrict__ W0, const float* __restrict__ W1,
                       const float* __restrict__ W2, const float* __restrict__ W3) {
    long i4 = (long)blockIdx.x * blockDim.x + threadIdx.x;
    const float* src; long base4;
    if      (i4 < 5120000L) { src = W0; base4 = 0L; }
    else if (i4 < 6400000L) { src = W1; base4 = 5120000L; }
    else if (i4 < 8960000L) { src = W2; base4 = 6400000L; }
    else if (i4 < 9230940L) { src = W3; base4 = 8960000L; }
    else return;
    float4 v = ((const float4*)src)[i4 - base4];
    __nv_bfloat162 h0 = __floats2bfloat162_rn(v.x, v.y);
    __nv_bfloat162 h1 = __floats2bfloat162_rn(v.z, v.w);
    uint2 u;
    u.x = *reinterpret_cast<uint32_t*>(&h0);
    u.y = *reinterpret_cast<uint32_t*>(&h1);
    ((uint2*)g_Wh)[i4] = u;
}

// ---------------- K1: ALL projections fused: Y = H(512x1024) @ Pcat^T ----
__global__ void k_proj_all(const float* __restrict__ H,
                           const float* __restrict__ P0, const float* __restrict__ P1,
                           const float* __restrict__ P2, const float* __restrict__ P3) {
    __shared__ float As[16][66];
    __shared__ float Bs[16][66];

    const int nt = blockIdx.x;
    const float* P; int E, yofs, n0;
    if (nt < 16)       { P = P0; E = 1024; yofs = 0;    n0 = nt * 64; }
    else if (nt < 20)  { P = P1; E = 256;  yofs = 1024; n0 = (nt - 16) * 64; }
    else if (nt == 20) { P = P2; E = 64;   yofs = 1280; n0 = 0; }
    else               { P = P3; E = 16;   yofs = 1344; n0 = 0; }

    const int tid = threadIdx.x;
    const int tx = tid & 15, ty = tid >> 4;
    const int m0 = blockIdx.y * 64;

    float acc[4][4];
#pragma unroll
    for (int i = 0; i < 4; i++)
#pragma unroll
        for (int j = 0; j < 4; j++) acc[i][j] = 0.f;

    for (int k0 = 0; k0 < 1024; k0 += 16) {
#pragma unroll
        for (int i = 0; i < 4; i++) {
            int e = tid + i * 256;
            int r = e >> 4, c = e & 15;
            As[c][r] = H[(size_t)(m0 + r) * 1024 + k0 + c];
            int nn = n0 + r;
            Bs[c][r] = (nn < E) ? P[(size_t)nn * 1024 + k0 + c] : 0.f;
        }
        __syncthreads();
#pragma unroll
        for (int k = 0; k < 16; k++) {
            float am[4], bn[4];
#pragma unroll
            for (int i = 0; i < 4; i++) am[i] = As[k][ty * 4 + i];
#pragma unroll
            for (int j = 0; j < 4; j++) bn[j] = Bs[k][tx * 4 + j];
#pragma unroll
            for (int i = 0; i < 4; i++)
#pragma unroll
                for (int j = 0; j < 4; j++) acc[i][j] += am[i] * bn[j];
        }
        __syncthreads();
    }
#pragma unroll
    for (int i = 0; i < 4; i++) {
        int m = m0 + ty * 4 + i;
#pragma unroll
        for (int j = 0; j < 4; j++) {
            int n = n0 + tx * 4 + j;
            if (n < E) {
                size_t idx = (size_t)m * YSTRIDE + yofs + n;
                g_Yf[idx] = acc[i][j];
                g_Yh[idx] = __float2bfloat16(acc[i][j]);
            }
        }
    }
}

// ---------------- K2: logits GEMM, cp.async double-buffered smem pipeline ------
// Block tile 64 rows x 256 cols, 8 warps (each 64x32 unique cols).
// Pipeline steps = (n-tiles per block) x (K / kc), kc = min(K,64).
// Both A and B staged via cp.async.cg; fragments via ldmatrix.x4.
// mode 0: store RAW logits + rowsums   (r0/r1 pass 1)
// mode 1: rowsums only                 (r2/r3 pass 1)
// mode 2: store FINAL logit - SUB      (r2/r3 pass 2)
__global__ __launch_bounds__(256, 2)
void k_logits(const __nv_bfloat16* __restrict__ W, const float* __restrict__ b,
              float* __restrict__ out,
              int N, int K, int yofs, int colBase, int region, int mode,
              int ntPerBlk) {
    extern __shared__ char smem_raw[];
    const uint32_t smemBase = (uint32_t)__cvta_generic_to_shared(smem_raw);
    float* srow = (float*)(smem_raw + 2 * STG);

    const int tid  = threadIdx.x;
    const int lane = tid & 31, wid = tid >> 5;
    const int mBlk = blockIdx.x * 64;

    const int kc      = (K < 64) ? K : 64;
    const int nchunks = K / kc;
    int numT = (N + 255) / 256 - blockIdx.y * ntPerBlk;
    if (numT > ntPerBlk) numT = ntPerBlk;
    const int total = numT * nchunks;
    const int cpr = kc >> 3;          // uint4 chunks per row

    const int qr  = lane >> 2;        // 0..7
    const int qc2 = (lane & 3) * 2;   // 0,2,4,6

    // ldmatrix lane bases (buffer-relative)
    const uint32_t aLane = (uint32_t)(((lane & 15) * LDA + ((lane >> 4) << 3)) * 2);
    const int bRow  = wid * 32 + (lane & 7) + ((lane >> 4) << 3);  // + ntpair*16
    const uint32_t bLane = (uint32_t)((bRow * LDB + (((lane >> 3) & 1) << 3)) * 2);

    // ---- stage one pipeline step into buffer ----
    auto stage = [&](int s, int buf) {
        int t = s / nchunks;
        int kc0 = (s - t * nchunks) * kc;
        int nB = (blockIdx.y * ntPerBlk + t) * 256;
        uint32_t base = smemBase + buf * STG;
        for (int i = tid; i < 64 * cpr; i += 256) {
            int r = i / cpr, c = i - r * cpr;
            cp16(base + (uint32_t)((r * LDA + c * 8) * 2),
                 g_Yh + (size_t)(mBlk + r) * YSTRIDE + yofs + kc0 + c * 8, 16);
        }
        for (int i = tid; i < 256 * cpr; i += 256) {
            int r = i / cpr, c = i - r * cpr;
            int n = nB + r;
            const __nv_bfloat16* src =
                W + (size_t)(n < N ? n : 0) * K + kc0 + c * 8;
            cp16(base + (uint32_t)(ABYTES + (r * LDB + c * 8) * 2),
                 src, (n < N) ? 16 : 0);
        }
        asm volatile("cp.async.commit_group;\n" ::: "memory");
    };

    float acc[4][4][4];
#pragma unroll
    for (int mt = 0; mt < 4; mt++)
#pragma unroll
        for (int nt = 0; nt < 4; nt++)
#pragma unroll
            for (int c = 0; c < 4; c++) acc[mt][nt][c] = 0.f;

    stage(0, 0);
    int buf = 0;

    for (int s = 0; s < total; s++) {
        const int t = s / nchunks;
        const int kchunk = s - t * nchunks;

        asm volatile("cp.async.wait_group 0;\n" ::: "memory");
        __syncthreads();

        if (s + 1 < total) stage(s + 1, buf ^ 1);

        // ---- compute on current buffer ----
        const uint32_t aBase = smemBase + buf * STG + aLane;
        const uint32_t bBase = smemBase + buf * STG + ABYTES + bLane;
        const int nk = kc >> 4;
        for (int ks = 0; ks < nk; ks++) {
            const int k0 = ks * 16;
            uint32_t a[4][4];
#pragma unroll
            for (int mt = 0; mt < 4; mt++) {
                uint32_t addr = aBase + (uint32_t)((mt * 16 * LDA + k0) * 2);
                asm volatile(
                    "ldmatrix.sync.aligned.m8n8.x4.shared.b16 "
                    "{%0,%1,%2,%3}, [%4];"
                    : "=r"(a[mt][0]), "=r"(a[mt][1]),
                      "=r"(a[mt][2]), "=r"(a[mt][3])
                    : "r"(addr));
            }
            uint32_t fB[4][2];
#pragma unroll
            for (int pair = 0; pair < 2; pair++) {
                uint32_t addr = bBase + (uint32_t)((pair * 16 * LDB + k0) * 2);
                asm volatile(
                    "ldmatrix.sync.aligned.m8n8.x4.shared.b16 "
                    "{%0,%1,%2,%3}, [%4];"
                    : "=r"(fB[pair * 2][0]),     "=r"(fB[pair * 2][1]),
                      "=r"(fB[pair * 2 + 1][0]), "=r"(fB[pair * 2 + 1][1])
                    : "r"(addr));
            }
#pragma unroll
            for (int mt = 0; mt < 4; mt++)
#pragma unroll
                for (int nt = 0; nt < 4; nt++) {
                    asm volatile(
                        "mma.sync.aligned.m16n8k16.row.col.f32.bf16.bf16.f32 "
                        "{%0,%1,%2,%3}, {%4,%5,%6,%7}, {%8,%9}, {%0,%1,%2,%3};\n"
                        : "+f"(acc[mt][nt][0]), "+f"(acc[mt][nt][1]),
                          "+f"(acc[mt][nt][2]), "+f"(acc[mt][nt][3])
                        : "r"(a[mt][0]), "r"(a[mt][1]), "r"(a[mt][2]), "r"(a[mt][3]),
                          "r"(fB[nt][0]), "r"(fB[nt][1]));
                }
        }

        // ---- epilogue on last k-chunk of this n-tile ----
        if (kchunk == nchunks - 1) {
            const int nBlk = (blockIdx.y * ntPerBlk + t) * 256;
            if (mode == 2) {
#pragma unroll
                for (int mt = 0; mt < 4; mt++) {
#pragma unroll
                    for (int hh = 0; hh < 2; hh++) {
                        int rloc = mt * 16 + qr + hh * 8;
                        size_t rgl = (size_t)(mBlk + rloc);
                        float sub = g_SUB[region * NROWS + rgl];
#pragma unroll
                        for (int nt = 0; nt < 4; nt++) {
                            int n0 = nBlk + wid * 32 + nt * 8 + qc2;
#pragma unroll
                            for (int p = 0; p < 2; p++) {
                                int n = n0 + p;
                                if (n < N)
                                    out[rgl * V_TOTAL + colBase + n] =
                                        acc[mt][nt][hh * 2 + p] + b[n] - sub;
                            }
                        }
                    }
                }
            } else {
                __syncthreads();
                if (tid < 64) srow[tid] = 0.f;
                __syncthreads();
#pragma unroll
                for (int mt = 0; mt < 4; mt++) {
#pragma unroll
                    for (int hh = 0; hh < 2; hh++) {
                        int rloc = mt * 16 + qr + hh * 8;
                        size_t rgl = (size_t)(mBlk + rloc);
                        float part = 0.f;
#pragma unroll
                        for (int nt = 0; nt < 4; nt++) {
                            int n0 = nBlk + wid * 32 + nt * 8 + qc2;
#pragma unroll
                            for (int p = 0; p < 2; p++) {
                                int n = n0 + p;
                                if (n < N) {
                                    float v = acc[mt][nt][hh * 2 + p] + b[n];
                                    if (mode == 0)
                                        out[rgl * V_TOTAL + colBase + n] = v;
                                    part += __expf(v);
                                }
                            }
                        }
                        part += __shfl_xor_sync(0xffffffffu, part, 1);
                        part += __shfl_xor_sync(0xffffffffu, part, 2);
                        if ((lane & 3) == 0) atomicAdd(&srow[rloc], part);
                    }
                }
                __syncthreads();
                if (tid < 64)
                    atomicAdd(&g_rowsum[region * NROWS + mBlk + tid], srow[tid]);
            }
            // reset accumulators for next n-tile
#pragma unroll
            for (int mt = 0; mt < 4; mt++)
#pragma unroll
                for (int nt = 0; nt < 4; nt++)
#pragma unroll
                    for (int c = 0; c < 4; c++) acc[mt][nt][c] = 0.f;
        }
        buf ^= 1;
    }
}

// ---------------- K3: cluster logits + per-region subtract terms ----------------
__global__ void k_head_fix(const float* __restrict__ cw, const float* __restrict__ cb) {
    const int row = blockIdx.x;
    const int tid = threadIdx.x;  // 128
    __shared__ float red[3][128];
    float p0 = 0.f, p1 = 0.f, p2 = 0.f;
    const float* y = g_Yf + (size_t)row * YSTRIDE;
    for (int e = tid; e < 1024; e += 128) {
        float yv = y[e];
        p0 += yv * cw[e];
        p1 += yv * cw[1024 + e];
        p2 += yv * cw[2048 + e];
    }
    red[0][tid] = p0; red[1][tid] = p1; red[2][tid] = p2;
    __syncthreads();
    for (int s = 64; s > 0; s >>= 1) {
        if (tid < s) {
            red[0][tid] += red[0][tid + s];
            red[1][tid] += red[1][tid + s];
            red[2][tid] += red[2][tid + s];
        }
        __syncthreads();
    }
    if (tid == 0) {
        float c0 = red[0][0] + cb[0];
        float c1 = red[1][0] + cb[1];
        float c2 = red[2][0] + cb[2];
        float s = g_rowsum[row] + __expf(c0) + __expf(c1) + __expf(c2);
        float lse0 = logf(s);
        g_SUB[row] = lse0;
        float cl[3] = {c0 - lse0, c1 - lse0, c2 - lse0};
        for (int i = 1; i < 4; i++)
            g_SUB[i * NROWS + row] = logf(g_rowsum[i * NROWS + row]) - cl[i - 1];
    }
}

// ---------------- K4: subtract over regions 0/1 only (cols < 40000) ----------------
__global__ void k_sub01(float* __restrict__ out) {
    int i = blockIdx.x * blockDim.x + threadIdx.x;
    if (i >= NROWS * 40000) return;
    int row = i / 40000;
    int col = i - row * 40000;
    int reg = (col < 20000) ? 0 : 1;
    out[(size_t)row * V_TOTAL + col] -= g_SUB[reg * NROWS + row];
}

// ---------------- K5: loss = mean(-lp[target]) ----------------
__global__ void k_loss(const float* __restrict__ out, const int* __restrict__ tgt,
                       float* __restrict__ loss_out) {
    __shared__ float red[512];
    int r = threadIdx.x;
    int t = tgt[r];
    red[r] = -out[(size_t)r * V_TOTAL + t];
    __syncthreads();
    for (int s = 256; s > 0; s >>= 1) {
        if (r < s) red[r] += red[r + s];
        __syncthreads();
    }
    if (r == 0) *loss_out = red[0] / 512.f;
}

// ---------------- launch ----------------
extern "C" void kernel_launch(void* const* d_in, const int* in_sizes, int n_in,
                              void* d_out, int out_size) {
    const float* hidden = (const float*)d_in[0];
    const int*   target = (const int*)d_in[1];
    const float* cw     = (const float*)d_in[2];
    const float* cb     = (const float*)d_in[3];
    const float* W[4]  = {(const float*)d_in[4],  (const float*)d_in[7],
                          (const float*)d_in[10], (const float*)d_in[13]};
    const float* bb[4] = {(const float*)d_in[5],  (const float*)d_in[8],
                          (const float*)d_in[11], (const float*)d_in[14]};
    const float* P[4]  = {(const float*)d_in[6],  (const float*)d_in[9],
                          (const float*)d_in[12], (const float*)d_in[15]};
    float* out = (float*)d_out;

    static const int  Ns[4]      = {20000, 20000, 160000, 67735};
    static const int  Ks[4]      = {1024, 256, 64, 16};
    static const int  yofs[4]    = {0, 1024, 1280, 1344};
    static const int  colBase[4] = {0, 20000, 40000, 200000};
    static const long wofs[4]    = {0L, 20480000L, 25600000L, 35840000L};
    static const int  NT[4]      = {1, 1, 8, 4};   // 256-col tiles per block

    cudaFuncSetAttribute(k_logits, cudaFuncAttributeMaxDynamicSharedMemorySize,
                         LOGITS_SMEM);

    k_zero<<<8, 256>>>();
    k_cvtW<<<(9230940 + 255) / 256, 256>>>(W[0], W[1], W[2], W[3]);
    k_proj_all<<<dim3(22, 8), 256>>>(hidden, P[0], P[1], P[2], P[3]);

    // resolve g_Wh device address for pointer arithmetic on host
    __nv_bfloat16* whBase = nullptr;
    cudaGetSymbolAddress((void**)&whBase, g_Wh);

    // pass 1: r0/r1 raw store + rowsum (mode 0); r2/r3 rowsum only (mode 1)
    for (int i = 0; i < 4; i++) {
        int ntiles = (Ns[i] + 255) / 256;
        dim3 grid(8, (ntiles + NT[i] - 1) / NT[i]);
        int mode = (i < 2) ? 0 : 1;
        k_logits<<<grid, 256, LOGITS_SMEM>>>(whBase + wofs[i], bb[i], out,
                                             Ns[i], Ks[i], yofs[i],
                                             colBase[i], i, mode, NT[i]);
    }

    k_head_fix<<<512, 128>>>(cw, cb);

    // pass 2: subtract r0/r1; recompute + final store r2/r3
    k_sub01<<<(NROWS * 40000 + 255) / 256, 256>>>(out);
    for (int i = 2; i < 4; i++) {
        int ntiles = (Ns[i] + 255) / 256;
        dim3 grid(8, (ntiles + NT[i] - 1) / NT[i]);
        k_logits<<<grid, 256, LOGITS_SMEM>>>(whBase + wofs[i], bb[i], out,
                                             Ns[i], Ks[i], yofs[i],
                                             colBase[i], i, 2, NT[i]);
    }

    k_loss<<<1, 512>>>(out, target, out + (size_t)out_size - 1);
}

// round 15
// speedup vs baseline: 1.7312x; 1.0469x over previous
#include <cuda_runtime.h>
#include <cuda_bf16.h>
#include <cstdint>

#define V_TOTAL 267735
#define NROWS   512
#define YSTRIDE 1360   // 1024 + 256 + 64 + 16

// W bf16 scratch: 20000*1024 + 20000*256 + 160000*64 + 67735*16 = 36,923,760
#define WH_TOTAL 36923760

// k_logits smem geometry (kc <= 64)
#define LDA 72
#define LDB 72
#define ABYTES (64 * LDA * 2)          // 9216
#define BBYTES (256 * LDB * 2)         // 36864
#define STG    (ABYTES + BBYTES)       // 46080 per stage
#define LOGITS_SMEM (2 * STG + 256)    // double buffer + srow

// ---------------- device scratch (no allocations allowed) ----------------
__device__ float          g_Yf[NROWS * YSTRIDE];   // fp32 projections (head cluster)
__device__ __nv_bfloat16  g_Yh[NROWS * YSTRIDE];   // bf16 projections (GEMM A)
__device__ __nv_bfloat16  g_Wh[WH_TOTAL];          // bf16 weights (GEMM B)
__device__ float          g_rowsum[4 * NROWS];     // sum(exp(logit)) per region/row
__device__ float          g_SUB[4 * NROWS];        // per-region per-row subtract term

__device__ __forceinline__ void cp16(uint32_t dst, const void* src, int srcBytes) {
    asm volatile("cp.async.cg.shared.global [%0], [%1], 16, %2;\n"
                 :: "r"(dst), "l"(src), "r"(srcBytes));
}

// ---------------- K0: zero the row sums ----------------
__global__ void k_zero() {
    int i = blockIdx.x * blockDim.x + threadIdx.x;
    if (i < 4 * NROWS) g_rowsum[i] = 0.f;
}

// ---------------- K0b: convert all W to bf16 (float4 -> 4x bf16) ----------------
__global__ void k_cvtW(const float* __restrict__ W0, const float* __restrict__ W1,
                       const float* __restrict__ W2, const float* __restrict__ W3) {
    long i4 = (long)blockIdx.x * blockDim.x + threadIdx.x;
    const float* src; long base4;
    if      (i4 < 5120000L) { src = W0; base4 = 0L; }
    else if (i4 < 6400000L) { src = W1; base4 = 5120000L; }
    else if (i4 < 8960000L) { src = W2; base4 = 6400000L; }
    else if (i4 < 9230940L) { src = W3; base4 = 8960000L; }
    else return;
    float4 v = ((const float4*)src)[i4 - base4];
    __nv_bfloat162 h0 = __floats2bfloat162_rn(v.x, v.y);
    __nv_bfloat162 h1 = __floats2bfloat162_rn(v.z, v.w);
    uint2 u;
    u.x = *reinterpret_cast<uint32_t*>(&h0);
    u.y = *reinterpret_cast<uint32_t*>(&h1);
    ((uint2*)g_Wh)[i4] = u;
}

// ---------------- K1: ALL projections fused: Y = H(512x1024) @ Pcat^T ----
__global__ void k_proj_all(const float* __restrict__ H,
                           const float* __restrict__ P0, const float* __restrict__ P1,
                           const float* __restrict__ P2, const float* __restrict__ P3) {
    __shared__ float As[16][66];
    __shared__ float Bs[16][66];

    const int nt = blockIdx.x;
    const float* P; int E, yofs, n0;
    if (nt < 16)       { P = P0; E = 1024; yofs = 0;    n0 = nt * 64; }
    else if (nt < 20)  { P = P1; E = 256;  yofs = 1024; n0 = (nt - 16) * 64; }
    else if (nt == 20) { P = P2; E = 64;   yofs = 1280; n0 = 0; }
    else               { P = P3; E = 16;   yofs = 1344; n0 = 0; }

    const int tid = threadIdx.x;
    const int tx = tid & 15, ty = tid >> 4;
    const int m0 = blockIdx.y * 64;

    float acc[4][4];
#pragma unroll
    for (int i = 0; i < 4; i++)
#pragma unroll
        for (int j = 0; j < 4; j++) acc[i][j] = 0.f;

    for (int k0 = 0; k0 < 1024; k0 += 16) {
#pragma unroll
        for (int i = 0; i < 4; i++) {
            int e = tid + i * 256;
            int r = e >> 4, c = e & 15;
            As[c][r] = H[(size_t)(m0 + r) * 1024 + k0 + c];
            int nn = n0 + r;
            Bs[c][r] = (nn < E) ? P[(size_t)nn * 1024 + k0 + c] : 0.f;
        }
        __syncthreads();
#pragma unroll
        for (int k = 0; k < 16; k++) {
            float am[4], bn[4];
#pragma unroll
            for (int i = 0; i < 4; i++) am[i] = As[k][ty * 4 + i];
#pragma unroll
            for (int j = 0; j < 4; j++) bn[j] = Bs[k][tx * 4 + j];
#pragma unroll
            for (int i = 0; i < 4; i++)
#pragma unroll
                for (int j = 0; j < 4; j++) acc[i][j] += am[i] * bn[j];
        }
        __syncthreads();
    }
#pragma unroll
    for (int i = 0; i < 4; i++) {
        int m = m0 + ty * 4 + i;
#pragma unroll
        for (int j = 0; j < 4; j++) {
            int n = n0 + tx * 4 + j;
            if (n < E) {
                size_t idx = (size_t)m * YSTRIDE + yofs + n;
                g_Yf[idx] = acc[i][j];
                g_Yh[idx] = __float2bfloat16(acc[i][j]);
            }
        }
    }
}

// ---------------- K2: logits GEMM, templated on K and MODE ---------------------
// Block tile 64 rows x 256 cols, 8 warps (each 64x32 unique cols).
// cp.async double-buffered; all geometry compile-time.
// MODE 0: store RAW logits + rowsums   (r0/r1 pass 1)
// MODE 1: rowsums only                 (r2/r3 pass 1)
// MODE 2: store FINAL logit - SUB      (r2/r3 pass 2)
template<int K, int MODE>
__global__ __launch_bounds__(256, 2)
void k_logits(const __nv_bfloat16* __restrict__ W, const float* __restrict__ b,
              float* __restrict__ out,
              int N, int yofs, int colBase, int region, int ntPerBlk) {
    constexpr int KCC  = (K < 64) ? K : 64;   // k-chunk
    constexpr int NCH  = K / KCC;             // chunks per tile
    constexpr int CPR  = KCC / 8;             // uint4 per row
    constexpr int NK   = KCC / 16;            // ksteps per chunk
    constexpr int AIT  = (64 * CPR + 255) / 256;   // A stage iters/thread
    constexpr int BIT  = (256 * CPR) / 256;        // B stage iters/thread

    extern __shared__ char smem_raw[];
    const uint32_t smemBase = (uint32_t)__cvta_generic_to_shared(smem_raw);
    float* srow = (float*)(smem_raw + 2 * STG);

    const int tid  = threadIdx.x;
    const int lane = tid & 31, wid = tid >> 5;
    const int mBlk = blockIdx.x * 64;

    int numT = (N + 255) / 256 - blockIdx.y * ntPerBlk;
    if (numT > ntPerBlk) numT = ntPerBlk;
    const int total = numT * NCH;
    const int tile0 = blockIdx.y * ntPerBlk;

    const int qr  = lane >> 2;        // 0..7
    const int qc2 = (lane & 3) * 2;   // 0,2,4,6

    // ldmatrix lane bases (buffer-relative)
    const uint32_t aLane = (uint32_t)(((lane & 15) * LDA + ((lane >> 4) << 3)) * 2);
    const int bRow  = wid * 32 + (lane & 7) + ((lane >> 4) << 3);
    const uint32_t bLane = (uint32_t)((bRow * LDB + (((lane >> 3) & 1) << 3)) * 2);

    // ---- precomputed staging coordinates (compile-time strides) ----
    // A: element i = tid + it*256 -> r = i/CPR, c = i%CPR
    const __nv_bfloat16* aSrc[AIT];
    uint32_t aDst[AIT];
    bool aPred[AIT];
#pragma unroll
    for (int it = 0; it < AIT; it++) {
        int i = tid + it * 256;
        int r = i / CPR, c = i % CPR;
        aPred[it] = (i < 64 * CPR);
        aSrc[it]  = g_Yh + (size_t)(mBlk + (aPred[it] ? r : 0)) * YSTRIDE + yofs + c * 8;
        aDst[it]  = (uint32_t)((r * LDA + c * 8) * 2);
    }
    // B: element i -> r = i/CPR (W row within tile), c = i%CPR
    int bR[BIT];
    const __nv_bfloat16* bSrc[BIT];   // W + r*K + c*8 (add nB*K + kc0 per step)
    uint32_t bDst[BIT];
#pragma unroll
    for (int it = 0; it < BIT; it++) {
        int i = tid + it * 256;
        int r = i / CPR, c = i % CPR;
        bR[it]   = r;
        bSrc[it] = W + (size_t)r * K + c * 8;
        bDst[it] = (uint32_t)(ABYTES + (r * LDB + c * 8) * 2);
    }

    auto stageA = [&](int kc0, int buf) {
        uint32_t base = smemBase + buf * STG;
#pragma unroll
        for (int it = 0; it < AIT; it++)
            if (aPred[it]) cp16(base + aDst[it], aSrc[it] + kc0, 16);
    };
    auto stageB = [&](int s, int buf) {
        int t, kc0;
        if (NCH == 1) { t = s; kc0 = 0; }
        else          { t = s / NCH; kc0 = (s - t * NCH) * KCC; }
        int nB = (tile0 + t) * 256;
        uint32_t base = smemBase + buf * STG;
#pragma unroll
        for (int it = 0; it < BIT; it++) {
            int n = nB + bR[it];
            cp16(base + bDst[it],
                 bSrc[it] + ((n < N) ? ((size_t)nB * K + kc0) : (size_t)(-(long)bR[it] * K)),
                 (n < N) ? 16 : 0);
        }
    };

    float acc[4][4][4];
#pragma unroll
    for (int mt = 0; mt < 4; mt++)
#pragma unroll
        for (int nt = 0; nt < 4; nt++)
#pragma unroll
            for (int c = 0; c < 4; c++) acc[mt][nt][c] = 0.f;

    // prologue: A once into both buffers when it never changes (NCH==1)
    if (NCH == 1) { stageA(0, 0); stageA(0, 1); }
    else          stageA(0, 0);
    stageB(0, 0);
    asm volatile("cp.async.commit_group;\n" ::: "memory");

    int buf = 0;
    for (int s = 0; s < total; s++) {
        int t, kchunk;
        if (NCH == 1) { t = s; kchunk = 0; }
        else          { t = s / NCH; kchunk = s - t * NCH; }

        asm volatile("cp.async.wait_group 0;\n" ::: "memory");
        __syncthreads();

        if (s + 1 < total) {
            if (NCH > 1) {
                int t1 = (s + 1) / NCH;
                stageA(((s + 1) - t1 * NCH) * KCC, buf ^ 1);
            }
            stageB(s + 1, buf ^ 1);
            asm volatile("cp.async.commit_group;\n" ::: "memory");
        }

        // ---- compute on current buffer ----
        const uint32_t aBase = smemBase + buf * STG + aLane;
        const uint32_t bBase = smemBase + buf * STG + ABYTES + bLane;
#pragma unroll
        for (int ks = 0; ks < NK; ks++) {
            const int k0 = ks * 16;
            uint32_t a[4][4];
#pragma unroll
            for (int mt = 0; mt < 4; mt++) {
                uint32_t addr = aBase + (uint32_t)((mt * 16 * LDA + k0) * 2);
                asm volatile(
                    "ldmatrix.sync.aligned.m8n8.x4.shared.b16 "
                    "{%0,%1,%2,%3}, [%4];"
                    : "=r"(a[mt][0]), "=r"(a[mt][1]),
                      "=r"(a[mt][2]), "=r"(a[mt][3])
                    : "r"(addr));
            }
            uint32_t fB[4][2];
#pragma unroll
            for (int pair = 0; pair < 2; pair++) {
                uint32_t addr = bBase + (uint32_t)((pair * 16 * LDB + k0) * 2);
                asm volatile(
                    "ldmatrix.sync.aligned.m8n8.x4.shared.b16 "
                    "{%0,%1,%2,%3}, [%4];"
                    : "=r"(fB[pair * 2][0]),     "=r"(fB[pair * 2][1]),
                      "=r"(fB[pair * 2 + 1][0]), "=r"(fB[pair * 2 + 1][1])
                    : "r"(addr));
            }
#pragma unroll
            for (int mt = 0; mt < 4; mt++)
#pragma unroll
                for (int nt = 0; nt < 4; nt++) {
                    asm volatile(
                        "mma.sync.aligned.m16n8k16.row.col.f32.bf16.bf16.f32 "
                        "{%0,%1,%2,%3}, {%4,%5,%6,%7}, {%8,%9}, {%0,%1,%2,%3};\n"
                        : "+f"(acc[mt][nt][0]), "+f"(acc[mt][nt][1]),
                          "+f"(acc[mt][nt][2]), "+f"(acc[mt][nt][3])
                        : "r"(a[mt][0]), "r"(a[mt][1]), "r"(a[mt][2]), "r"(a[mt][3]),
                          "r"(fB[nt][0]), "r"(fB[nt][1]));
                }
        }

        // ---- epilogue on last k-chunk of this n-tile ----
        if (kchunk == NCH - 1) {
            const int nBlk = (tile0 + t) * 256;
            if (MODE == 2) {
#pragma unroll
                for (int mt = 0; mt < 4; mt++) {
#pragma unroll
                    for (int hh = 0; hh < 2; hh++) {
                        int rloc = mt * 16 + qr + hh * 8;
                        size_t rgl = (size_t)(mBlk + rloc);
                        float sub = g_SUB[region * NROWS + rgl];
#pragma unroll
                        for (int nt = 0; nt < 4; nt++) {
                            int n0 = nBlk + wid * 32 + nt * 8 + qc2;
#pragma unroll
                            for (int p = 0; p < 2; p++) {
                                int n = n0 + p;
                                if (n < N)
                                    out[rgl * V_TOTAL + colBase + n] =
                                        acc[mt][nt][hh * 2 + p] + b[n] - sub;
                            }
                        }
                    }
                }
            } else {
                __syncthreads();
                if (tid < 64) srow[tid] = 0.f;
                __syncthreads();
#pragma unroll
                for (int mt = 0; mt < 4; mt++) {
#pragma unroll
                    for (int hh = 0; hh < 2; hh++) {
                        int rloc = mt * 16 + qr + hh * 8;
                        size_t rgl = (size_t)(mBlk + rloc);
                        float part = 0.f;
#pragma unroll
                        for (int nt = 0; nt < 4; nt++) {
                            int n0 = nBlk + wid * 32 + nt * 8 + qc2;
#pragma unroll
                            for (int p = 0; p < 2; p++) {
                                int n = n0 + p;
                                if (n < N) {
                                    float v = acc[mt][nt][hh * 2 + p] + b[n];
                                    if (MODE == 0)
                                        out[rgl * V_TOTAL + colBase + n] = v;
                                    part += __expf(v);
                                }
                            }
                        }
                        part += __shfl_xor_sync(0xffffffffu, part, 1);
                        part += __shfl_xor_sync(0xffffffffu, part, 2);
                        if ((lane & 3) == 0) atomicAdd(&srow[rloc], part);
                    }
                }
                __syncthreads();
                if (tid < 64)
                    atomicAdd(&g_rowsum[region * NROWS + mBlk + tid], srow[tid]);
            }
#pragma unroll
            for (int mt = 0; mt < 4; mt++)
#pragma unroll
                for (int nt = 0; nt < 4; nt++)
#pragma unroll
                    for (int c = 0; c < 4; c++) acc[mt][nt][c] = 0.f;
        }
        buf ^= 1;
    }
}

// ---------------- K3: cluster logits + per-region subtract terms ----------------
__global__ void k_head_fix(const float* __restrict__ cw, const float* __restrict__ cb) {
    const int row = blockIdx.x;
    const int tid = threadIdx.x;  // 128
    __shared__ float red[3][128];
    float p0 = 0.f, p1 = 0.f, p2 = 0.f;
    const float* y = g_Yf + (size_t)row * YSTRIDE;
    for (int e = tid; e < 1024; e += 128) {
        float yv = y[e];
        p0 += yv * cw[e];
        p1 += yv * cw[1024 + e];
        p2 += yv * cw[2048 + e];
    }
    red[0][tid] = p0; red[1][tid] = p1; red[2][tid] = p2;
    __syncthreads();
    for (int s = 64; s > 0; s >>= 1) {
        if (tid < s) {
            red[0][tid] += red[0][tid + s];
            red[1][tid] += red[1][tid + s];
            red[2][tid] += red[2][tid + s];
        }
        __syncthreads();
    }
    if (tid == 0) {
        float c0 = red[0][0] + cb[0];
        float c1 = red[1][0] + cb[1];
        float c2 = red[2][0] + cb[2];
        float s = g_rowsum[row] + __expf(c0) + __expf(c1) + __expf(c2);
        float lse0 = logf(s);
        g_SUB[row] = lse0;
        float cl[3] = {c0 - lse0, c1 - lse0, c2 - lse0};
        for (int i = 1; i < 4; i++)
            g_SUB[i * NROWS + row] = logf(g_rowsum[i * NROWS + row]) - cl[i - 1];
    }
}

// ---------------- K4: subtract over regions 0/1 only (cols < 40000) ----------------
__global__ void k_sub01(float* __restrict__ out) {
    int i = blockIdx.x * blockDim.x + threadIdx.x;
    if (i >= NROWS * 40000) return;
    int row = i / 40000;
    int col = i - row * 40000;
    int reg = (col < 20000) ? 0 : 1;
    out[(size_t)row * V_TOTAL + col] -= g_SUB[reg * NROWS + row];
}

// ---------------- K5: loss = mean(-lp[target]) ----------------
__global__ void k_loss(const float* __restrict__ out, const int* __restrict__ tgt,
                       float* __restrict__ loss_out) {
    __shared__ float red[512];
    int r = threadIdx.x;
    int t = tgt[r];
    red[r] = -out[(size_t)r * V_TOTAL + t];
    __syncthreads();
    for (int s = 256; s > 0; s >>= 1) {
        if (r < s) red[r] += red[r + s];
        __syncthreads();
    }
    if (r == 0) *loss_out = red[0] / 512.f;
}

// ---------------- launch ----------------
extern "C" void kernel_launch(void* const* d_in, const int* in_sizes, int n_in,
                              void* d_out, int out_size) {
    const float* hidden = (const float*)d_in[0];
    const int*   target = (const int*)d_in[1];
    const float* cw     = (const float*)d_in[2];
    const float* cb     = (const float*)d_in[3];
    const float* W[4]  = {(const float*)d_in[4],  (const float*)d_in[7],
                          (const float*)d_in[10], (const float*)d_in[13]};
    const float* bb[4] = {(const float*)d_in[5],  (const float*)d_in[8],
                          (const float*)d_in[11], (const float*)d_in[14]};
    const float* P[4]  = {(const float*)d_in[6],  (const float*)d_in[9],
                          (const float*)d_in[12], (const float*)d_in[15]};
    float* out = (float*)d_out;

    static const int  Ns[4]      = {20000, 20000, 160000, 67735};
    static const int  yofs[4]    = {0, 1024, 1280, 1344};
    static const int  colBase[4] = {0, 20000, 40000, 200000};
    static const long wofs[4]    = {0L, 20480000L, 25600000L, 35840000L};
    static const int  NT[4]      = {1, 1, 8, 4};   // 256-col tiles per block

    cudaFuncSetAttribute(k_logits<1024,0>, cudaFuncAttributeMaxDynamicSharedMemorySize, LOGITS_SMEM);
    cudaFuncSetAttribute(k_logits<256,0>,  cudaFuncAttributeMaxDynamicSharedMemorySize, LOGITS_SMEM);
    cudaFuncSetAttribute(k_logits<64,1>,   cudaFuncAttributeMaxDynamicSharedMemorySize, LOGITS_SMEM);
    cudaFuncSetAttribute(k_logits<16,1>,   cudaFuncAttributeMaxDynamicSharedMemorySize, LOGITS_SMEM);
    cudaFuncSetAttribute(k_logits<64,2>,   cudaFuncAttributeMaxDynamicSharedMemorySize, LOGITS_SMEM);
    cudaFuncSetAttribute(k_logits<16,2>,   cudaFuncAttributeMaxDynamicSharedMemorySize, LOGITS_SMEM);

    k_zero<<<8, 256>>>();
    k_cvtW<<<(9230940 + 255) / 256, 256>>>(W[0], W[1], W[2], W[3]);
    k_proj_all<<<dim3(22, 8), 256>>>(hidden, P[0], P[1], P[2], P[3]);

    // resolve g_Wh device address for pointer arithmetic on host
    __nv_bfloat16* whBase = nullptr;
    cudaGetSymbolAddress((void**)&whBase, g_Wh);

    auto grid_for = [&](int i) {
        int ntiles = (Ns[i] + 255) / 256;
        return dim3(8, (ntiles + NT[i] - 1) / NT[i]);
    };

    // pass 1: r0/r1 raw store + rowsum (mode 0); r2/r3 rowsum only (mode 1)
    k_logits<1024,0><<<grid_for(0), 256, LOGITS_SMEM>>>(whBase + wofs[0], bb[0], out,
                                                        Ns[0], yofs[0], colBase[0], 0, NT[0]);
    k_logits<256,0><<<grid_for(1), 256, LOGITS_SMEM>>>(whBase + wofs[1], bb[1], out,
                                                       Ns[1], yofs[1], colBase[1], 1, NT[1]);
    k_logits<64,1><<<grid_for(2), 256, LOGITS_SMEM>>>(whBase + wofs[2], bb[2], out,
                                                      Ns[2], yofs[2], colBase[2], 2, NT[2]);
    k_logits<16,1><<<grid_for(3), 256, LOGITS_SMEM>>>(whBase + wofs[3], bb[3], out,
                                                      Ns[3], yofs[3], colBase[3], 3, NT[3]);

    k_head_fix<<<512, 128>>>(cw, cb);

    // pass 2: subtract r0/r1; recompute + final store r2/r3
    k_sub01<<<(NROWS * 40000 + 255) / 256, 256>>>(out);
    k_logits<64,2><<<grid_for(2), 256, LOGITS_SMEM>>>(whBase + wofs[2], bb[2], out,
                                                      Ns[2], yofs[2], colBase[2], 2, NT[2]);
    k_logits<16,2><<<grid_for(3), 256, LOGITS_SMEM>>>(whBase + wofs[3], bb[3], out,
                                                      Ns[3], yofs[3], colBase[3], 3, NT[3]);

    k_loss<<<1, 512>>>(out, target, out + (size_t)out_size - 1);
}